// round 6
// baseline (speedup 1.0000x reference)
#include <cuda_runtime.h>
#include <math.h>

#define S_LEN    2048
#define DH       64
#define NB       2
#define NH       8
#define WIN      128
#define TQ       64
#define NTHREADS 512
#define NWARPS   16
#define NCHUNK   9

// Shared memory (floats): K^T + Q^T + p-staging only (V read from gmem/L2)
#define KTS     319                  // K^T row stride (odd -> conflict-free)
#define QTS     68
#define SM_KT   (DH * KTS)           // 20416
#define SM_QT   (DH * QTS)           // 4352
#define SM_PS   (NWARPS * 128)       // 2048
#define SM_FLOATS (SM_KT + SM_QT + SM_PS)
#define SMEM_BYTES (SM_FLOATS * 4)   // 107264 -> 2 CTAs/SM

// packed f32x2 FMA: d = a*b + d  (FFMA2)
__device__ __forceinline__ void ffma2(float2& d, float2 a, float2 b) {
    asm("{\n\t"
        ".reg .b64 ra, rb, rd;\n\t"
        "mov.b64 ra, {%2, %3};\n\t"
        "mov.b64 rb, {%4, %5};\n\t"
        "mov.b64 rd, {%0, %1};\n\t"
        "fma.rn.f32x2 rd, ra, rb, rd;\n\t"
        "mov.b64 {%0, %1}, rd;\n\t"
        "}"
        : "+f"(d.x), "+f"(d.y)
        : "f"(a.x), "f"(a.y), "f"(b.x), "f"(b.y));
}

__global__ void __launch_bounds__(NTHREADS, 2)
band_attn_kernel(const float* __restrict__ Q,
                 const float* __restrict__ K,
                 const float* __restrict__ V,
                 float* __restrict__ ctx_out,
                 float* __restrict__ attn_out)
{
    extern __shared__ float smem[];
    float* Kt = smem;                 // [DH][KTS]
    float* Qt = Kt + SM_KT;           // [DH][QTS]
    float* Ps = Qt + SM_QT;           // [16 warps][128]

    const int tid  = threadIdx.x;
    const int w    = tid >> 5;
    const int lane = tid & 31;
    const int bh   = blockIdx.z * NH + blockIdx.y;
    const int q0   = blockIdx.x * TQ;

    const int k_lo = max(0, q0 - (WIN - 1));
    const int k_hi = min(S_LEN - 1, q0 + TQ - 1 + (WIN - 1));
    const int cnt  = k_hi - k_lo + 1;   // <= 318

    const float* Qg = Q + (size_t)bh * S_LEN * DH;
    const float* Kg = K + (size_t)bh * S_LEN * DH;
    const float* Vg = V + (size_t)bh * S_LEN * DH;

    // ---- load K^T and Q^T tiles ----
    for (int idx = tid; idx < TQ * DH; idx += NTHREADS) {
        int q = idx >> 6, d = idx & 63;
        Qt[d * QTS + q] = Qg[(size_t)(q0 + q) * DH + d];
    }
    for (int idx = tid; idx < cnt * DH; idx += NTHREADS) {
        int kk = idx >> 6, d = idx & 63;
        Kt[d * KTS + kk] = Kg[(size_t)(k_lo + kk) * DH + d];
    }

    // ---- zero-fill attn outside each row's band ----
    float* attn_base = attn_out + (size_t)bh * S_LEN * S_LEN;
    {
        float* tile0 = attn_base + (size_t)q0 * S_LEN;
        const float4 z4 = make_float4(0.f, 0.f, 0.f, 0.f);
        #pragma unroll 4
        for (int r = 0; r < TQ; ++r) {
            int qg = q0 + r;
            int lo = max(0, qg - (WIN - 1));
            int hi = min(S_LEN - 1, qg + (WIN - 1));
            if (4 * tid + 3 < lo || 4 * tid > hi)
                ((float4*)(tile0 + (size_t)r * S_LEN))[tid] = z4;
        }
        if (tid < TQ) {
            int qg = q0 + tid;
            int lo = max(0, qg - (WIN - 1));
            int hi = min(S_LEN - 1, qg + (WIN - 1));
            float* row = tile0 + (size_t)tid * S_LEN;
            for (int c = lo & ~3; c < lo; ++c) row[c] = 0.f;
            int e = (hi + 4) & ~3;
            if (e > S_LEN) e = S_LEN;
            for (int c = hi + 1; c < e; ++c) row[c] = 0.f;
        }
    }
    __syncthreads();

    // ---- per-warp: 4 consecutive queries ----
    const int qbase = w * 4;
    const int qg0   = q0 + qbase;
    const int a = max(0, qg0 - (WIN - 1)) - k_lo;
    const int b = min(S_LEN - 1, qg0 + 3 + (WIN - 1)) - k_lo;

    // ---- scores (packed f32x2) ----
    float2 s01[NCHUNK], s23[NCHUNK];
    #pragma unroll
    for (int c = 0; c < NCHUNK; ++c) {
        s01[c] = make_float2(0.f, 0.f);
        s23[c] = make_float2(0.f, 0.f);
    }
    #pragma unroll 4
    for (int d = 0; d < DH; ++d) {
        const float4 qv = *(const float4*)(Qt + d * QTS + qbase);
        const float2 q01 = make_float2(qv.x, qv.y);
        const float2 q23 = make_float2(qv.z, qv.w);
        const float* Krow = Kt + d * KTS + a + lane;
        #pragma unroll
        for (int c = 0; c < NCHUNK; ++c) {
            float kv = Krow[c * 32];
            float2 k2 = make_float2(kv, kv);
            ffma2(s01[c], q01, k2);
            ffma2(s23[c], q23, k2);
        }
    }

    // ---- scale + band mask ----
    #pragma unroll
    for (int c = 0; c < NCHUNK; ++c) {
        int kk = a + c * 32 + lane;
        int k  = k_lo + kk;
        bool inr = (kk <= b);
        bool v0 = inr && (k >= qg0     - (WIN-1)) && (k <= qg0     + (WIN-1));
        bool v1 = inr && (k >= qg0 + 1 - (WIN-1)) && (k <= qg0 + 1 + (WIN-1));
        bool v2 = inr && (k >= qg0 + 2 - (WIN-1)) && (k <= qg0 + 2 + (WIN-1));
        bool v3 = inr && (k >= qg0 + 3 - (WIN-1)) && (k <= qg0 + 3 + (WIN-1));
        s01[c].x = v0 ? s01[c].x * 0.125f : -INFINITY;
        s01[c].y = v1 ? s01[c].y * 0.125f : -INFINITY;
        s23[c].x = v2 ? s23[c].x * 0.125f : -INFINITY;
        s23[c].y = v3 ? s23[c].y * 0.125f : -INFINITY;
    }

    // ---- softmax ----
    {
        float2 mx = make_float2(-INFINITY, -INFINITY);
        #pragma unroll
        for (int c = 0; c < NCHUNK; ++c) {
            mx.x = fmaxf(mx.x, s01[c].x); mx.y = fmaxf(mx.y, s01[c].y);
        }
        #pragma unroll
        for (int off = 16; off > 0; off >>= 1) {
            mx.x = fmaxf(mx.x, __shfl_xor_sync(0xffffffffu, mx.x, off));
            mx.y = fmaxf(mx.y, __shfl_xor_sync(0xffffffffu, mx.y, off));
        }
        float2 sm = make_float2(0.f, 0.f);
        #pragma unroll
        for (int c = 0; c < NCHUNK; ++c) {
            s01[c].x = __expf(s01[c].x - mx.x); sm.x += s01[c].x;
            s01[c].y = __expf(s01[c].y - mx.y); sm.y += s01[c].y;
        }
        #pragma unroll
        for (int off = 16; off > 0; off >>= 1) {
            sm.x += __shfl_xor_sync(0xffffffffu, sm.x, off);
            sm.y += __shfl_xor_sync(0xffffffffu, sm.y, off);
        }
        float2 inv = make_float2(1.f / sm.x, 1.f / sm.y);
        #pragma unroll
        for (int c = 0; c < NCHUNK; ++c) { s01[c].x *= inv.x; s01[c].y *= inv.y; }
    }
    {
        float2 mx = make_float2(-INFINITY, -INFINITY);
        #pragma unroll
        for (int c = 0; c < NCHUNK; ++c) {
            mx.x = fmaxf(mx.x, s23[c].x); mx.y = fmaxf(mx.y, s23[c].y);
        }
        #pragma unroll
        for (int off = 16; off > 0; off >>= 1) {
            mx.x = fmaxf(mx.x, __shfl_xor_sync(0xffffffffu, mx.x, off));
            mx.y = fmaxf(mx.y, __shfl_xor_sync(0xffffffffu, mx.y, off));
        }
        float2 sm = make_float2(0.f, 0.f);
        #pragma unroll
        for (int c = 0; c < NCHUNK; ++c) {
            s23[c].x = __expf(s23[c].x - mx.x); sm.x += s23[c].x;
            s23[c].y = __expf(s23[c].y - mx.y); sm.y += s23[c].y;
        }
        #pragma unroll
        for (int off = 16; off > 0; off >>= 1) {
            sm.x += __shfl_xor_sync(0xffffffffu, sm.x, off);
            sm.y += __shfl_xor_sync(0xffffffffu, sm.y, off);
        }
        float2 inv = make_float2(1.f / sm.x, 1.f / sm.y);
        #pragma unroll
        for (int c = 0; c < NCHUNK; ++c) { s23[c].x *= inv.x; s23[c].y *= inv.y; }
    }

    // ---- write attn band values ----
    #pragma unroll
    for (int c = 0; c < NCHUNK; ++c) {
        int kk = a + c * 32 + lane;
        int k  = k_lo + kk;
        bool inr = (kk <= b);
        if (inr && k >= qg0     - (WIN-1) && k <= qg0     + (WIN-1))
            attn_base[(size_t)(qg0    ) * S_LEN + k] = s01[c].x;
        if (inr && k >= qg0 + 1 - (WIN-1) && k <= qg0 + 1 + (WIN-1))
            attn_base[(size_t)(qg0 + 1) * S_LEN + k] = s01[c].y;
        if (inr && k >= qg0 + 2 - (WIN-1) && k <= qg0 + 2 + (WIN-1))
            attn_base[(size_t)(qg0 + 2) * S_LEN + k] = s23[c].x;
        if (inr && k >= qg0 + 3 - (WIN-1) && k <= qg0 + 3 + (WIN-1))
            attn_base[(size_t)(qg0 + 3) * S_LEN + k] = s23[c].y;
    }

    // ---- context: V from gmem (L2-hot), lane owns dims (2l, 2l+1) ----
    float2 cq0 = make_float2(0.f, 0.f), cq1 = make_float2(0.f, 0.f);
    float2 cq2 = make_float2(0.f, 0.f), cq3 = make_float2(0.f, 0.f);

    float* myPs = Ps + w * 128;
    const float* Vrow0 = Vg + (size_t)k_lo * DH + 2 * lane;
    #pragma unroll
    for (int c = 0; c < NCHUNK; ++c) {
        const int kkb = a + c * 32;
        if (kkb > b) continue;
        *(float4*)(myPs + lane * 4) = make_float4(s01[c].x, s01[c].y, s23[c].x, s23[c].y);
        __syncwarp();
        #pragma unroll 8
        for (int j = 0; j < 32; ++j) {
            int kr = min(kkb + j, cnt - 1);          // clamp: p==0 past the edge
            float2 v  = *(const float2*)(Vrow0 + (size_t)kr * DH);
            float4 p  = *(const float4*)(myPs + j * 4);
            ffma2(cq0, make_float2(p.x, p.x), v);
            ffma2(cq1, make_float2(p.y, p.y), v);
            ffma2(cq2, make_float2(p.z, p.z), v);
            ffma2(cq3, make_float2(p.w, p.w), v);
        }
        __syncwarp();
    }

    float* ctx_base = ctx_out + ((size_t)bh * S_LEN + qg0) * DH + 2 * lane;
    *(float2*)(ctx_base + 0 * DH) = cq0;
    *(float2*)(ctx_base + 1 * DH) = cq1;
    *(float2*)(ctx_base + 2 * DH) = cq2;
    *(float2*)(ctx_base + 3 * DH) = cq3;
}

extern "C" void kernel_launch(void* const* d_in, const int* in_sizes, int n_in,
                              void* d_out, int out_size)
{
    const float* Q = (const float*)d_in[0];
    const float* K = (const float*)d_in[1];
    const float* V = (const float*)d_in[2];

    float* out  = (float*)d_out;
    float* ctx  = out;                                 // [B,H,S,D] first
    float* attn = out + (size_t)NB * NH * S_LEN * DH;  // then [B,H,S,S]

    cudaFuncSetAttribute(band_attn_kernel,
                         cudaFuncAttributeMaxDynamicSharedMemorySize, SMEM_BYTES);

    dim3 grid(S_LEN / TQ, NH, NB);
    band_attn_kernel<<<grid, NTHREADS, SMEM_BYTES>>>(Q, K, V, ctx, attn);
}

// round 8
// speedup vs baseline: 1.0030x; 1.0030x over previous
#include <cuda_runtime.h>
#include <math.h>

#define S_LEN    2048
#define DH       64
#define NB       2
#define NH       8
#define WIN      128
#define TQ       64
#define NTHREADS 512
#define NC       5        // chunks per warp half

// shared layout (floats)
#define KTS      319      // K^T row stride, odd -> conflict-free
#define QTS      68
#define F_KT     (DH * KTS)        // 20416
#define F_QT     (DH * QTS)        // 4352 (Cpart overlay: 4096 needed)
#define F_PS     (16 * 128)        // 2048
#define O_QT     F_KT
#define O_PS     (O_QT + F_QT)
#define O_MS     (O_PS + F_PS)     // float2[16][4]
#define O_SS     (O_MS + 128)
#define SM_FLOATS (O_SS + 128)     // 27072
#define SMEM_BYTES (SM_FLOATS * 4) // 108288 -> 2 CTAs/SM

__device__ __forceinline__ void ffma2(float2& d, float2 a, float2 b) {
    asm("{\n\t.reg .b64 ra, rb, rd;\n\t"
        "mov.b64 ra, {%2, %3};\n\tmov.b64 rb, {%4, %5};\n\tmov.b64 rd, {%0, %1};\n\t"
        "fma.rn.f32x2 rd, ra, rb, rd;\n\tmov.b64 {%0, %1}, rd;\n\t}"
        : "+f"(d.x), "+f"(d.y) : "f"(a.x), "f"(a.y), "f"(b.x), "f"(b.y));
}

__global__ void __launch_bounds__(NTHREADS, 2)
band_attn_kernel(const float* __restrict__ Q,
                 const float* __restrict__ K,
                 const float* __restrict__ V,
                 float* __restrict__ ctx_out,
                 float* __restrict__ attn_out)
{
    extern __shared__ float smem[];
    float*  Kt  = smem;
    float*  Qt  = smem + O_QT;
    float*  Ps  = smem + O_PS;
    float2* Ms2 = (float2*)(smem + O_MS);
    float2* Ss2 = (float2*)(smem + O_SS);
    float*  Cp  = Qt;                      // overlay: [8 groups][8 q][64 d]

    const int tid  = threadIdx.x;
    const int w    = tid >> 5;
    const int lane = tid & 31;
    const int bh   = blockIdx.z * NH + blockIdx.y;
    const int q0   = blockIdx.x * TQ;

    const int k_lo = max(0, q0 - (WIN - 1));
    const int k_hi = min(S_LEN - 1, q0 + TQ - 1 + (WIN - 1));
    const int cnt  = k_hi - k_lo + 1;      // <= 318

    const float* Qg = Q + (size_t)bh * S_LEN * DH;
    const float* Kg = K + (size_t)bh * S_LEN * DH;
    const float* Vg = V + (size_t)bh * S_LEN * DH;

    // ---- tiles ----
    for (int idx = tid; idx < TQ * 16; idx += NTHREADS) {      // Q: float4 reads
        int q = idx >> 4, dq = idx & 15;
        float4 v = ((const float4*)Qg)[(q0 + q) * 16 + dq];
        Qt[(4 * dq + 0) * QTS + q] = v.x;
        Qt[(4 * dq + 1) * QTS + q] = v.y;
        Qt[(4 * dq + 2) * QTS + q] = v.z;
        Qt[(4 * dq + 3) * QTS + q] = v.w;
    }
    for (int idx = tid; idx < cnt * DH; idx += NTHREADS) {     // K^T
        int kk = idx >> 6, d = idx & 63;
        Kt[d * KTS + kk] = Kg[(size_t)(k_lo + kk) * DH + d];
    }

    // ---- zero-fill attn outside each row's band ----
    float* attn_base = attn_out + (size_t)bh * S_LEN * S_LEN;
    {
        float* tile0 = attn_base + (size_t)q0 * S_LEN;
        const float4 z4 = make_float4(0.f, 0.f, 0.f, 0.f);
        #pragma unroll 4
        for (int r = 0; r < TQ; ++r) {
            int qg = q0 + r;
            int lo = max(0, qg - (WIN - 1));
            int hi = min(S_LEN - 1, qg + (WIN - 1));
            if (4 * tid + 3 < lo || 4 * tid > hi)
                ((float4*)(tile0 + (size_t)r * S_LEN))[tid] = z4;
        }
        if (tid < TQ) {
            int qg = q0 + tid;
            int lo = max(0, qg - (WIN - 1));
            int hi = min(S_LEN - 1, qg + (WIN - 1));
            float* row = tile0 + (size_t)tid * S_LEN;
            for (int c = lo & ~3; c < lo; ++c) row[c] = 0.f;
            int e = (hi + 4) & ~3;
            if (e > S_LEN) e = S_LEN;
            for (int c = hi + 1; c < e; ++c) row[c] = 0.f;
        }
    }
    __syncthreads();

    // ---- warp roles: group g (8 queries), half h (chunk range) ----
    const int g  = w >> 1;
    const int h  = w & 1;
    const int qg0 = q0 + g * 8;
    const int a  = max(0, qg0 - (WIN - 1)) - k_lo;
    const int b  = min(S_LEN - 1, qg0 + 7 + (WIN - 1)) - k_lo;
    const int cbase = a + 32 * (h * NC);   // h=0: chunks 0..4, h=1: 5..9

    // ---- scores: s[c][p] -> queries (2p, 2p+1) ----
    float2 s[NC][4];
    #pragma unroll
    for (int c = 0; c < NC; ++c)
        #pragma unroll
        for (int p = 0; p < 4; ++p) s[c][p] = make_float2(0.f, 0.f);

    #pragma unroll 4
    for (int d = 0; d < DH; ++d) {
        const float4 qv0 = *(const float4*)(Qt + d * QTS + g * 8);
        const float4 qv1 = *(const float4*)(Qt + d * QTS + g * 8 + 4);
        const float* Krow = Kt + d * KTS + cbase + lane;
        #pragma unroll
        for (int c = 0; c < NC; ++c) {
            float kv = Krow[c * 32];
            float2 k2 = make_float2(kv, kv);
            ffma2(s[c][0], make_float2(qv0.x, qv0.y), k2);
            ffma2(s[c][1], make_float2(qv0.z, qv0.w), k2);
            ffma2(s[c][2], make_float2(qv1.x, qv1.y), k2);
            ffma2(s[c][3], make_float2(qv1.z, qv1.w), k2);
        }
    }

    // ---- scale + band mask (k < S_LEN guards clamped-tail blocks) ----
    #pragma unroll
    for (int c = 0; c < NC; ++c) {
        int k = k_lo + cbase + c * 32 + lane;
        bool kv = (k < S_LEN);
        #pragma unroll
        for (int p = 0; p < 4; ++p) {
            bool vx = kv && (unsigned)(qg0 + 2 * p     - k + WIN - 1) <= 2 * (WIN - 1);
            bool vy = kv && (unsigned)(qg0 + 2 * p + 1 - k + WIN - 1) <= 2 * (WIN - 1);
            s[c][p].x = vx ? s[c][p].x * 0.125f : -INFINITY;
            s[c][p].y = vy ? s[c][p].y * 0.125f : -INFINITY;
        }
    }

    // ---- local max + local sum ----
    float2 mx[4], sl[4];
    #pragma unroll
    for (int p = 0; p < 4; ++p) mx[p] = make_float2(-INFINITY, -INFINITY);
    #pragma unroll
    for (int c = 0; c < NC; ++c)
        #pragma unroll
        for (int p = 0; p < 4; ++p) {
            mx[p].x = fmaxf(mx[p].x, s[c][p].x);
            mx[p].y = fmaxf(mx[p].y, s[c][p].y);
        }
    #pragma unroll
    for (int off = 16; off > 0; off >>= 1)
        #pragma unroll
        for (int p = 0; p < 4; ++p) {
            mx[p].x = fmaxf(mx[p].x, __shfl_xor_sync(0xffffffffu, mx[p].x, off));
            mx[p].y = fmaxf(mx[p].y, __shfl_xor_sync(0xffffffffu, mx[p].y, off));
        }
    #pragma unroll
    for (int p = 0; p < 4; ++p) {          // clamp so empty halves stay finite
        mx[p].x = fmaxf(mx[p].x, -1e30f);
        mx[p].y = fmaxf(mx[p].y, -1e30f);
        sl[p] = make_float2(0.f, 0.f);
    }
    #pragma unroll
    for (int c = 0; c < NC; ++c)
        #pragma unroll
        for (int p = 0; p < 4; ++p) {
            sl[p].x += __expf(s[c][p].x - mx[p].x);
            sl[p].y += __expf(s[c][p].y - mx[p].y);
        }
    #pragma unroll
    for (int off = 16; off > 0; off >>= 1)
        #pragma unroll
        for (int p = 0; p < 4; ++p) {
            sl[p].x += __shfl_xor_sync(0xffffffffu, sl[p].x, off);
            sl[p].y += __shfl_xor_sync(0xffffffffu, sl[p].y, off);
        }
    #pragma unroll
    for (int p = 0; p < 4; ++p)
        if (lane == p) { Ms2[w * 4 + p] = mx[p]; Ss2[w * 4 + p] = sl[p]; }
    __syncthreads();

    // ---- combine halves: C = M + ln(S)  (p = exp(s - C)) ----
    float2 C[4];
    #pragma unroll
    for (int p = 0; p < 4; ++p) {
        float2 m0 = Ms2[(g * 2) * 4 + p], m1 = Ms2[(g * 2 + 1) * 4 + p];
        float2 s0 = Ss2[(g * 2) * 4 + p], s1 = Ss2[(g * 2 + 1) * 4 + p];
        float Mx = fmaxf(m0.x, m1.x), My = fmaxf(m0.y, m1.y);
        float Sx = s0.x * __expf(m0.x - Mx) + s1.x * __expf(m1.x - Mx);
        float Sy = s0.y * __expf(m0.y - My) + s1.y * __expf(m1.y - My);
        C[p] = make_float2(Mx + __logf(Sx), My + __logf(Sy));
    }

    // ---- p = exp(s - C) (0 outside band); write attn band ----
    #pragma unroll
    for (int c = 0; c < NC; ++c) {
        int k = k_lo + cbase + c * 32 + lane;
        bool kv = (k < S_LEN);
        #pragma unroll
        for (int p = 0; p < 4; ++p) {
            bool vx = kv && (unsigned)(qg0 + 2 * p     - k + WIN - 1) <= 2 * (WIN - 1);
            bool vy = kv && (unsigned)(qg0 + 2 * p + 1 - k + WIN - 1) <= 2 * (WIN - 1);
            s[c][p].x = vx ? __expf(s[c][p].x - C[p].x) : 0.f;
            s[c][p].y = vy ? __expf(s[c][p].y - C[p].y) : 0.f;
            if (vx) attn_base[(size_t)(qg0 + 2 * p    ) * S_LEN + k] = s[c][p].x;
            if (vy) attn_base[(size_t)(qg0 + 2 * p + 1) * S_LEN + k] = s[c][p].y;
        }
    }

    // ---- context partial: V from gmem, p via per-warp staging (2 rounds/chunk) ----
    float2 cq[8];
    #pragma unroll
    for (int i = 0; i < 8; ++i) cq[i] = make_float2(0.f, 0.f);

    float* myPs = Ps + w * 128;
    const float* Vrow0 = Vg + (size_t)k_lo * DH + 2 * lane;
    #pragma unroll
    for (int c = 0; c < NC; ++c) {
        const int kkb = cbase + c * 32;
        if (kkb > b) continue;
        #pragma unroll
        for (int rr = 0; rr < 2; ++rr) {
            if ((lane >> 4) == rr) {
                int sl16 = (lane & 15) * 8;
                *(float4*)(myPs + sl16)     = make_float4(s[c][0].x, s[c][0].y, s[c][1].x, s[c][1].y);
                *(float4*)(myPs + sl16 + 4) = make_float4(s[c][2].x, s[c][2].y, s[c][3].x, s[c][3].y);
            }
            __syncwarp();
            #pragma unroll 8
            for (int j = 0; j < 16; ++j) {
                int kr = min(kkb + rr * 16 + j, cnt - 1);   // clamp; p==0 past edge
                float2 v  = *(const float2*)(Vrow0 + (size_t)kr * DH);
                float4 pA = *(const float4*)(myPs + j * 8);
                float4 pB = *(const float4*)(myPs + j * 8 + 4);
                ffma2(cq[0], make_float2(pA.x, pA.x), v);
                ffma2(cq[1], make_float2(pA.y, pA.y), v);
                ffma2(cq[2], make_float2(pA.z, pA.z), v);
                ffma2(cq[3], make_float2(pA.w, pA.w), v);
                ffma2(cq[4], make_float2(pB.x, pB.x), v);
                ffma2(cq[5], make_float2(pB.y, pB.y), v);
                ffma2(cq[6], make_float2(pB.z, pB.z), v);
                ffma2(cq[7], make_float2(pB.w, pB.w), v);
            }
            __syncwarp();
        }
    }

    // ---- combine halves' context; h=0 writes out ----
    if (h == 1) {
        #pragma unroll
        for (int i = 0; i < 8; ++i)
            *(float2*)(Cp + (g * 8 + i) * 64 + 2 * lane) = cq[i];
    }
    __syncthreads();
    if (h == 0) {
        float* ctx_base = ctx_out + ((size_t)bh * S_LEN + qg0) * DH + 2 * lane;
        #pragma unroll
        for (int i = 0; i < 8; ++i) {
            float2 pr = *(const float2*)(Cp + (g * 8 + i) * 64 + 2 * lane);
            cq[i].x += pr.x; cq[i].y += pr.y;
            *(float2*)(ctx_base + i * DH) = cq[i];
        }
    }
}

extern "C" void kernel_launch(void* const* d_in, const int* in_sizes, int n_in,
                              void* d_out, int out_size)
{
    const float* Q = (const float*)d_in[0];
    const float* K = (const float*)d_in[1];
    const float* V = (const float*)d_in[2];

    float* out  = (float*)d_out;
    float* ctx  = out;                                 // [B,H,S,D] first
    float* attn = out + (size_t)NB * NH * S_LEN * DH;  // then [B,H,S,S]

    cudaFuncSetAttribute(band_attn_kernel,
                         cudaFuncAttributeMaxDynamicSharedMemorySize, SMEM_BYTES);

    dim3 grid(S_LEN / TQ, NH, NB);
    band_attn_kernel<<<grid, NTHREADS, SMEM_BYTES>>>(Q, K, V, ctx, attn);
}

// round 9
// speedup vs baseline: 1.0619x; 1.0588x over previous
#include <cuda_runtime.h>
#include <math.h>
#include <stdint.h>

#define S_LEN 2048
#define DH    64
#define NB    2
#define NH    8
#define WIN   128
#define TQ    64
#define NT    1024
#define KW    320        // padded key window (k_lo = max(0,q0-128), even)
#define KP    68         // K/Q smem row pad (floats) -> conflict-free frag loads

// smem float offsets
#define O_K   0          // K tile [320][68] fp32 (ctx-combine slots overlay later)
#define O_QH  21760      // Q hi tf32-as-float [64][68]
#define O_QL  26112      // Q lo
#define O_STG 30464      // per-warp p staging: 32 x 160
#define O_MS  35584      // [8 nw][64 rows] local max
#define O_SS  36096      // local sum
#define SM_FL 36608
#define SMEM_B (SM_FL * 4)   // 146432 B

__device__ __forceinline__ uint32_t tf32c(float x) {
    uint32_t r; asm("cvt.rna.tf32.f32 %0, %1;" : "=r"(r) : "f"(x)); return r;
}
__device__ __forceinline__ void mma8(float* c, uint32_t a0, uint32_t a1, uint32_t a2, uint32_t a3,
                                     uint32_t b0, uint32_t b1) {
    asm("mma.sync.aligned.m16n8k8.row.col.f32.tf32.tf32.f32 "
        "{%0,%1,%2,%3}, {%4,%5,%6,%7}, {%8,%9}, {%0,%1,%2,%3};"
        : "+f"(c[0]), "+f"(c[1]), "+f"(c[2]), "+f"(c[3])
        : "r"(a0), "r"(a1), "r"(a2), "r"(a3), "r"(b0), "r"(b1));
}
__device__ __forceinline__ void ffma2(float2& d, float2 a, float2 b) {
    asm("{.reg .b64 ra,rb,rd; mov.b64 ra,{%2,%3}; mov.b64 rb,{%4,%5}; mov.b64 rd,{%0,%1};"
        " fma.rn.f32x2 rd,ra,rb,rd; mov.b64 {%0,%1},rd;}"
        : "+f"(d.x), "+f"(d.y) : "f"(a.x), "f"(a.y), "f"(b.x), "f"(b.y));
}

__global__ void __launch_bounds__(NT, 1)
band_attn_mma(const float* __restrict__ Q, const float* __restrict__ K,
              const float* __restrict__ V, float* __restrict__ ctx_out,
              float* __restrict__ attn_out)
{
    extern __shared__ float smem[];
    float* Ksm = smem + O_K;
    float* Qh  = smem + O_QH;
    float* Ql  = smem + O_QL;
    float* Ms  = smem + O_MS;
    float* Ss  = smem + O_SS;

    const int tid  = threadIdx.x, w = tid >> 5, lane = tid & 31;
    const int gid  = lane >> 2, tig = lane & 3;
    const int m    = w >> 3, nw = w & 7;      // 4 m-groups x 8 n-groups
    const int bh   = blockIdx.z * NH + blockIdx.y;
    const int q0   = blockIdx.x * TQ;
    const int klo  = max(0, q0 - 128);        // even, 4-aligned
    const int khi  = min(S_LEN - 1, q0 + TQ - 1 + WIN - 1);

    const float* Qg = Q + (size_t)bh * S_LEN * DH;
    const float* Kg = K + (size_t)bh * S_LEN * DH;
    const float* Vg = V + (size_t)bh * S_LEN * DH;
    float* attn = attn_out + (size_t)bh * S_LEN * S_LEN;

    const int cnt = khi - klo + 1;            // <= 319

    // ---- K tile (fp32) ----
    for (int i = tid; i < cnt * 16; i += NT) {
        int r = i >> 4, c = i & 15;
        float4 v = ((const float4*)Kg)[(klo + r) * 16 + c];
        float* d = Ksm + r * KP + 4 * c;
        d[0] = v.x; d[1] = v.y; d[2] = v.z; d[3] = v.w;
    }
    for (int i = cnt * KP + tid; i < KW * KP; i += NT) Ksm[i] = 0.f;  // zero pad rows

    // ---- Q tile: scale by 1/8, split hi/lo tf32 ----
    for (int i = tid; i < TQ * 16; i += NT) {
        int r = i >> 4, c = i & 15;
        float4 v = ((const float4*)Qg)[(q0 + r) * 16 + c];
        float* dh = Qh + r * KP + 4 * c;
        float* dl = Ql + r * KP + 4 * c;
        float x0 = v.x * 0.125f, x1 = v.y * 0.125f, x2 = v.z * 0.125f, x3 = v.w * 0.125f;
        float h0 = __uint_as_float(tf32c(x0)), h1 = __uint_as_float(tf32c(x1));
        float h2 = __uint_as_float(tf32c(x2)), h3 = __uint_as_float(tf32c(x3));
        dh[0] = h0; dh[1] = h1; dh[2] = h2; dh[3] = h3;
        dl[0] = __uint_as_float(tf32c(x0 - h0));
        dl[1] = __uint_as_float(tf32c(x1 - h1));
        dl[2] = __uint_as_float(tf32c(x2 - h2));
        dl[3] = __uint_as_float(tf32c(x3 - h3));
    }

    // ---- zero-fill outside the 320-wide strip (strip itself written by frag stores) ----
    {
        float* t0 = attn + (size_t)q0 * S_LEN;
        const int mm = tid & 511, rp = tid >> 9;
        if (4 * mm + 3 < klo || 4 * mm >= klo + KW) {
            const float4 z4 = make_float4(0.f, 0.f, 0.f, 0.f);
            #pragma unroll 4
            for (int r2 = 0; r2 < 32; ++r2)
                ((float4*)(t0 + (size_t)(2 * r2 + rp) * S_LEN))[mm] = z4;
        }
    }
    __syncthreads();

    // ---- scores: C[64x320] = Qs . K^T  via 3x tf32 mma ----
    float C[5][4];
    #pragma unroll
    for (int f = 0; f < 5; ++f)
        #pragma unroll
        for (int j = 0; j < 4; ++j) C[f][j] = 0.f;

    const int qr = m * 16;
    const int nb = nw * 40;
    #pragma unroll
    for (int ks = 0; ks < 8; ++ks) {
        const int kb = ks * 8;
        const float* ah = Qh + (qr + gid) * KP + kb + tig;
        const float* al = Ql + (qr + gid) * KP + kb + tig;
        uint32_t a0 = __float_as_uint(ah[0]),        a1 = __float_as_uint(ah[8 * KP]);
        uint32_t a2 = __float_as_uint(ah[4]),        a3 = __float_as_uint(ah[8 * KP + 4]);
        uint32_t l0 = __float_as_uint(al[0]),        l1 = __float_as_uint(al[8 * KP]);
        uint32_t l2 = __float_as_uint(al[4]),        l3 = __float_as_uint(al[8 * KP + 4]);
        #pragma unroll
        for (int f = 0; f < 5; ++f) {
            const float* bp = Ksm + (nb + f * 8 + gid) * KP + kb + tig;
            float b0f = bp[0], b1f = bp[4];
            uint32_t b0h = tf32c(b0f), b1h = tf32c(b1f);
            uint32_t b0l = tf32c(b0f - __uint_as_float(b0h));
            uint32_t b1l = tf32c(b1f - __uint_as_float(b1h));
            mma8(C[f], a0, a1, a2, a3, b0h, b1h);
            mma8(C[f], l0, l1, l2, l3, b0h, b1h);
            mma8(C[f], a0, a1, a2, a3, b0l, b1l);
        }
    }

    // ---- band mask + local row stats ----
    const int r0g = q0 + qr + gid;            // global row of c0/c1
    float mr0 = -INFINITY, mr1 = -INFINITY;
    #pragma unroll
    for (int f = 0; f < 5; ++f) {
        int k0 = klo + nb + f * 8 + 2 * tig;
        bool v0 = (unsigned)(r0g     - k0     + WIN - 1) <= 2 * (WIN - 1) && k0     <= khi;
        bool v1 = (unsigned)(r0g     - k0 - 1 + WIN - 1) <= 2 * (WIN - 1) && k0 + 1 <= khi;
        bool v2 = (unsigned)(r0g + 8 - k0     + WIN - 1) <= 2 * (WIN - 1) && k0     <= khi;
        bool v3 = (unsigned)(r0g + 8 - k0 - 1 + WIN - 1) <= 2 * (WIN - 1) && k0 + 1 <= khi;
        C[f][0] = v0 ? C[f][0] : -INFINITY;
        C[f][1] = v1 ? C[f][1] : -INFINITY;
        C[f][2] = v2 ? C[f][2] : -INFINITY;
        C[f][3] = v3 ? C[f][3] : -INFINITY;
        mr0 = fmaxf(mr0, fmaxf(C[f][0], C[f][1]));
        mr1 = fmaxf(mr1, fmaxf(C[f][2], C[f][3]));
    }
    #pragma unroll
    for (int off = 1; off <= 2; off <<= 1) {
        mr0 = fmaxf(mr0, __shfl_xor_sync(0xffffffffu, mr0, off));
        mr1 = fmaxf(mr1, __shfl_xor_sync(0xffffffffu, mr1, off));
    }
    mr0 = fmaxf(mr0, -1e30f); mr1 = fmaxf(mr1, -1e30f);
    float sr0 = 0.f, sr1 = 0.f;
    #pragma unroll
    for (int f = 0; f < 5; ++f) {
        sr0 += __expf(C[f][0] - mr0) + __expf(C[f][1] - mr0);
        sr1 += __expf(C[f][2] - mr1) + __expf(C[f][3] - mr1);
    }
    #pragma unroll
    for (int off = 1; off <= 2; off <<= 1) {
        sr0 += __shfl_xor_sync(0xffffffffu, sr0, off);
        sr1 += __shfl_xor_sync(0xffffffffu, sr1, off);
    }
    if (tig == 0) {
        Ms[nw * 64 + qr + gid]     = mr0;  Ss[nw * 64 + qr + gid]     = sr0;
        Ms[nw * 64 + qr + gid + 8] = mr1;  Ss[nw * 64 + qr + gid + 8] = sr1;
    }
    __syncthreads();

    // ---- global softmax constant per row: Cr = M + ln(S) ----
    float M0 = -INFINITY, M1 = -INFINITY;
    #pragma unroll
    for (int n2 = 0; n2 < 8; ++n2) {
        M0 = fmaxf(M0, Ms[n2 * 64 + qr + gid]);
        M1 = fmaxf(M1, Ms[n2 * 64 + qr + gid + 8]);
    }
    float S0 = 0.f, S1 = 0.f;
    #pragma unroll
    for (int n2 = 0; n2 < 8; ++n2) {
        S0 += Ss[n2 * 64 + qr + gid]     * __expf(Ms[n2 * 64 + qr + gid]     - M0);
        S1 += Ss[n2 * 64 + qr + gid + 8] * __expf(Ms[n2 * 64 + qr + gid + 8] - M1);
    }
    const float Cr0 = M0 + __logf(S0);
    const float Cr1 = M1 + __logf(S1);

    // ---- per frag: p = exp(c - Cr); store attn strip; stage; ctx partial ----
    float2 cq[16];
    #pragma unroll
    for (int i = 0; i < 16; ++i) cq[i] = make_float2(0.f, 0.f);

    float* stg = smem + O_STG + w * 160;     // [8 k][20] per warp
    const float* Vp = Vg + 2 * lane;
    #pragma unroll
    for (int f = 0; f < 5; ++f) {
        float p0 = __expf(C[f][0] - Cr0), p1 = __expf(C[f][1] - Cr0);
        float p2 = __expf(C[f][2] - Cr1), p3 = __expf(C[f][3] - Cr1);
        int k0 = klo + nb + f * 8 + 2 * tig;         // even -> float2 aligned
        if (k0 < S_LEN) {
            *(float2*)(attn + (size_t)r0g       * S_LEN + k0) = make_float2(p0, p1);
            *(float2*)(attn + (size_t)(r0g + 8) * S_LEN + k0) = make_float2(p2, p3);
        }
        stg[(2 * tig)     * 20 + gid]     = p0;
        stg[(2 * tig + 1) * 20 + gid]     = p1;
        stg[(2 * tig)     * 20 + gid + 8] = p2;
        stg[(2 * tig + 1) * 20 + gid + 8] = p3;
        __syncwarp();
        const int kb2 = klo + nb + f * 8;
        #pragma unroll
        for (int j = 0; j < 8; ++j) {
            int kr = min(kb2 + j, S_LEN - 1);        // clamp: p==0 past edge
            float2 v = *(const float2*)(Vp + (size_t)kr * DH);
            const float* ps = stg + j * 20;
            float4 pa = *(const float4*)(ps);
            float4 pb = *(const float4*)(ps + 4);
            float4 pc = *(const float4*)(ps + 8);
            float4 pd = *(const float4*)(ps + 12);
            ffma2(cq[0],  make_float2(pa.x, pa.x), v);
            ffma2(cq[1],  make_float2(pa.y, pa.y), v);
            ffma2(cq[2],  make_float2(pa.z, pa.z), v);
            ffma2(cq[3],  make_float2(pa.w, pa.w), v);
            ffma2(cq[4],  make_float2(pb.x, pb.x), v);
            ffma2(cq[5],  make_float2(pb.y, pb.y), v);
            ffma2(cq[6],  make_float2(pb.z, pb.z), v);
            ffma2(cq[7],  make_float2(pb.w, pb.w), v);
            ffma2(cq[8],  make_float2(pc.x, pc.x), v);
            ffma2(cq[9],  make_float2(pc.y, pc.y), v);
            ffma2(cq[10], make_float2(pc.z, pc.z), v);
            ffma2(cq[11], make_float2(pc.w, pc.w), v);
            ffma2(cq[12], make_float2(pd.x, pd.x), v);
            ffma2(cq[13], make_float2(pd.y, pd.y), v);
            ffma2(cq[14], make_float2(pd.z, pd.z), v);
            ffma2(cq[15], make_float2(pd.w, pd.w), v);
        }
        __syncwarp();
    }

    // ---- combine 8 nw partials (slots overlay dead K/Q regions) ----
    if (nw) {
        float* dst = smem + (m * 7 + nw - 1) * 1024;
        #pragma unroll
        for (int i = 0; i < 16; ++i)
            *(float2*)(dst + i * 64 + 2 * lane) = cq[i];
    }
    __syncthreads();
    if (!nw) {
        #pragma unroll
        for (int s = 0; s < 7; ++s) {
            const float* src = smem + (m * 7 + s) * 1024;
            #pragma unroll
            for (int i = 0; i < 16; ++i) {
                float2 t = *(const float2*)(src + i * 64 + 2 * lane);
                cq[i].x += t.x; cq[i].y += t.y;
            }
        }
        float* cb = ctx_out + ((size_t)bh * S_LEN + q0 + qr) * DH + 2 * lane;
        #pragma unroll
        for (int i = 0; i < 16; ++i)
            *(float2*)(cb + i * DH) = cq[i];
    }
}

extern "C" void kernel_launch(void* const* d_in, const int* in_sizes, int n_in,
                              void* d_out, int out_size)
{
    const float* Q = (const float*)d_in[0];
    const float* K = (const float*)d_in[1];
    const float* V = (const float*)d_in[2];

    float* out  = (float*)d_out;
    float* ctx  = out;                                 // [B,H,S,D] first
    float* attn = out + (size_t)NB * NH * S_LEN * DH;  // then [B,H,S,S]

    cudaFuncSetAttribute(band_attn_mma,
                         cudaFuncAttributeMaxDynamicSharedMemorySize, SMEM_B);

    dim3 grid(S_LEN / TQ, NH, NB);
    band_attn_mma<<<grid, NT, SMEM_B>>>(Q, K, V, ctx, attn);
}

// round 10
// speedup vs baseline: 1.2141x; 1.1433x over previous
#include <cuda_runtime.h>
#include <math.h>
#include <stdint.h>

#define S_LEN 2048
#define DH    64
#define NB    2
#define NH    8
#define WIN   128
#define TQ    64
#define NT    1024
#define KW    320
#define KP    68          // K/Q smem stride (floats)
#define VP    72          // V smem stride (floats) -> conflict-free ctx B frags

// smem float offsets
#define O_KH 0            // K hi tf32 [320][68]
#define O_KL 21760        // K lo
#define O_QH 43520        // Q hi [64][68]
#define O_QL 47872        // Q lo
#define O_MS 52224        // [8 nw][64]
#define O_SS 52736
#define SM_FL 53248
#define SMEM_B (SM_FL * 4)     // 212992 B
// overlays (after score phase K/Q are dead)
#define O_VH 0            // V hi tf32 [320][72] = 23040 fl
#define O_VL 23040        // V lo (ends 46080 < O_MS)
// combine slots overlay V region after ctx mma: 28 slots x 1024 fl

__device__ __forceinline__ uint32_t tf32c(float x) {
    uint32_t r; asm("cvt.rna.tf32.f32 %0, %1;" : "=r"(r) : "f"(x)); return r;
}
__device__ __forceinline__ float tf32f(float x) {
    uint32_t r = tf32c(x); return __uint_as_float(r);
}
__device__ __forceinline__ void mma8(float* c, uint32_t a0, uint32_t a1, uint32_t a2, uint32_t a3,
                                     uint32_t b0, uint32_t b1) {
    asm("mma.sync.aligned.m16n8k8.row.col.f32.tf32.tf32.f32 "
        "{%0,%1,%2,%3}, {%4,%5,%6,%7}, {%8,%9}, {%0,%1,%2,%3};"
        : "+f"(c[0]), "+f"(c[1]), "+f"(c[2]), "+f"(c[3])
        : "r"(a0), "r"(a1), "r"(a2), "r"(a3), "r"(b0), "r"(b1));
}
__device__ __forceinline__ void mma8v(float4& c, uint32_t a0, uint32_t a1, uint32_t a2, uint32_t a3,
                                      uint32_t b0, uint32_t b1) {
    asm("mma.sync.aligned.m16n8k8.row.col.f32.tf32.tf32.f32 "
        "{%0,%1,%2,%3}, {%4,%5,%6,%7}, {%8,%9}, {%0,%1,%2,%3};"
        : "+f"(c.x), "+f"(c.y), "+f"(c.z), "+f"(c.w)
        : "r"(a0), "r"(a1), "r"(a2), "r"(a3), "r"(b0), "r"(b1));
}

__global__ void __launch_bounds__(NT, 1)
band_attn_mma2(const float* __restrict__ Q, const float* __restrict__ K,
               const float* __restrict__ V, float* __restrict__ ctx_out,
               float* __restrict__ attn_out)
{
    extern __shared__ float smem[];
    const int tid  = threadIdx.x, w = tid >> 5, lane = tid & 31;
    const int gid  = lane >> 2, tig = lane & 3;
    const int m    = w >> 3, nw = w & 7;
    const int bh   = blockIdx.z * NH + blockIdx.y;
    const int q0   = blockIdx.x * TQ;
    const int klo  = max(0, q0 - 128);
    const int khi  = min(S_LEN - 1, q0 + TQ - 1 + WIN - 1);
    const int cnt  = khi - klo + 1;

    const float* Qg = Q + (size_t)bh * S_LEN * DH;
    const float* Kg = K + (size_t)bh * S_LEN * DH;
    const float* Vg = V + (size_t)bh * S_LEN * DH;
    float* attn = attn_out + (size_t)bh * S_LEN * S_LEN;

    // ---- K tile: pre-split tf32 hi/lo ----
    for (int i = tid; i < cnt * 16; i += NT) {
        int r = i >> 4, c = i & 15;
        float4 v = ((const float4*)Kg)[(klo + r) * 16 + c];
        float h0 = tf32f(v.x), h1 = tf32f(v.y), h2 = tf32f(v.z), h3 = tf32f(v.w);
        float* dh = smem + O_KH + r * KP + 4 * c;
        float* dl = smem + O_KL + r * KP + 4 * c;
        dh[0] = h0; dh[1] = h1; dh[2] = h2; dh[3] = h3;
        dl[0] = tf32f(v.x - h0); dl[1] = tf32f(v.y - h1);
        dl[2] = tf32f(v.z - h2); dl[3] = tf32f(v.w - h3);
    }
    for (int i = cnt * KP + tid; i < KW * KP; i += NT) {
        smem[O_KH + i] = 0.f; smem[O_KL + i] = 0.f;
    }
    // ---- Q tile: scale 1/8, split hi/lo ----
    for (int i = tid; i < TQ * 16; i += NT) {
        int r = i >> 4, c = i & 15;
        float4 v = ((const float4*)Qg)[(q0 + r) * 16 + c];
        float x0 = v.x * 0.125f, x1 = v.y * 0.125f, x2 = v.z * 0.125f, x3 = v.w * 0.125f;
        float h0 = tf32f(x0), h1 = tf32f(x1), h2 = tf32f(x2), h3 = tf32f(x3);
        float* dh = smem + O_QH + r * KP + 4 * c;
        float* dl = smem + O_QL + r * KP + 4 * c;
        dh[0] = h0; dh[1] = h1; dh[2] = h2; dh[3] = h3;
        dl[0] = tf32f(x0 - h0); dl[1] = tf32f(x1 - h1);
        dl[2] = tf32f(x2 - h2); dl[3] = tf32f(x3 - h3);
    }
    // ---- zero-fill attn outside the 320-wide strip ----
    {
        float* t0 = attn + (size_t)q0 * S_LEN;
        const int mm = tid & 511, rp = tid >> 9;
        if (4 * mm + 3 < klo || 4 * mm >= klo + KW) {
            const float4 z4 = make_float4(0.f, 0.f, 0.f, 0.f);
            #pragma unroll 4
            for (int r2 = 0; r2 < 32; ++r2)
                ((float4*)(t0 + (size_t)(2 * r2 + rp) * S_LEN))[mm] = z4;
        }
    }
    __syncthreads();

    // ---- score: C[64x320] = Qs . K^T (3-term tf32) ----
    float C[5][4];
    #pragma unroll
    for (int f = 0; f < 5; ++f) { C[f][0] = C[f][1] = C[f][2] = C[f][3] = 0.f; }
    const int qr = m * 16, nb = nw * 40;
    #pragma unroll
    for (int ks = 0; ks < 8; ++ks) {
        const int kb = ks * 8;
        const float* ah = smem + O_QH + (qr + gid) * KP + kb + tig;
        const float* al = smem + O_QL + (qr + gid) * KP + kb + tig;
        uint32_t a0 = __float_as_uint(ah[0]), a1 = __float_as_uint(ah[8 * KP]);
        uint32_t a2 = __float_as_uint(ah[4]), a3 = __float_as_uint(ah[8 * KP + 4]);
        uint32_t l0 = __float_as_uint(al[0]), l1 = __float_as_uint(al[8 * KP]);
        uint32_t l2 = __float_as_uint(al[4]), l3 = __float_as_uint(al[8 * KP + 4]);
        #pragma unroll
        for (int f = 0; f < 5; ++f) {
            const float* bh = smem + O_KH + (nb + f * 8 + gid) * KP + kb + tig;
            const float* bl = smem + O_KL + (nb + f * 8 + gid) * KP + kb + tig;
            uint32_t b0h = __float_as_uint(bh[0]), b1h = __float_as_uint(bh[4]);
            uint32_t b0l = __float_as_uint(bl[0]), b1l = __float_as_uint(bl[4]);
            mma8(C[f], a0, a1, a2, a3, b0h, b1h);
            mma8(C[f], l0, l1, l2, l3, b0h, b1h);
            mma8(C[f], a0, a1, a2, a3, b0l, b1l);
        }
    }

    // ---- band mask + local row stats ----
    const int r0g = q0 + qr + gid;
    float mr0 = -INFINITY, mr1 = -INFINITY;
    #pragma unroll
    for (int f = 0; f < 5; ++f) {
        int k0 = klo + nb + f * 8 + 2 * tig;
        bool v0 = (unsigned)(r0g     - k0     + WIN - 1) <= 2 * (WIN - 1) && k0     <= khi;
        bool v1 = (unsigned)(r0g     - k0 - 1 + WIN - 1) <= 2 * (WIN - 1) && k0 + 1 <= khi;
        bool v2 = (unsigned)(r0g + 8 - k0     + WIN - 1) <= 2 * (WIN - 1) && k0     <= khi;
        bool v3 = (unsigned)(r0g + 8 - k0 - 1 + WIN - 1) <= 2 * (WIN - 1) && k0 + 1 <= khi;
        C[f][0] = v0 ? C[f][0] : -INFINITY;
        C[f][1] = v1 ? C[f][1] : -INFINITY;
        C[f][2] = v2 ? C[f][2] : -INFINITY;
        C[f][3] = v3 ? C[f][3] : -INFINITY;
        mr0 = fmaxf(mr0, fmaxf(C[f][0], C[f][1]));
        mr1 = fmaxf(mr1, fmaxf(C[f][2], C[f][3]));
    }
    #pragma unroll
    for (int off = 1; off <= 2; off <<= 1) {
        mr0 = fmaxf(mr0, __shfl_xor_sync(0xffffffffu, mr0, off));
        mr1 = fmaxf(mr1, __shfl_xor_sync(0xffffffffu, mr1, off));
    }
    mr0 = fmaxf(mr0, -1e30f); mr1 = fmaxf(mr1, -1e30f);
    float sr0 = 0.f, sr1 = 0.f;
    #pragma unroll
    for (int f = 0; f < 5; ++f) {
        sr0 += __expf(C[f][0] - mr0) + __expf(C[f][1] - mr0);
        sr1 += __expf(C[f][2] - mr1) + __expf(C[f][3] - mr1);
    }
    #pragma unroll
    for (int off = 1; off <= 2; off <<= 1) {
        sr0 += __shfl_xor_sync(0xffffffffu, sr0, off);
        sr1 += __shfl_xor_sync(0xffffffffu, sr1, off);
    }
    if (tig == 0) {
        smem[O_MS + nw * 64 + qr + gid]     = mr0;  smem[O_SS + nw * 64 + qr + gid]     = sr0;
        smem[O_MS + nw * 64 + qr + gid + 8] = mr1;  smem[O_SS + nw * 64 + qr + gid + 8] = sr1;
    }
    __syncthreads();   // K/Q reads done; Ms/Ss visible

    // ---- V convert into (dead) K region: tf32 hi/lo, stride 72 ----
    for (int i = tid; i < KW * 16; i += NT) {
        int r = i >> 4, c = i & 15;
        float4 v = (r < cnt) ? ((const float4*)Vg)[(klo + r) * 16 + c]
                             : make_float4(0.f, 0.f, 0.f, 0.f);
        float h0 = tf32f(v.x), h1 = tf32f(v.y), h2 = tf32f(v.z), h3 = tf32f(v.w);
        float* dh = smem + O_VH + r * VP + 4 * c;
        float* dl = smem + O_VL + r * VP + 4 * c;
        dh[0] = h0; dh[1] = h1; dh[2] = h2; dh[3] = h3;
        dl[0] = tf32f(v.x - h0); dl[1] = tf32f(v.y - h1);
        dl[2] = tf32f(v.z - h2); dl[3] = tf32f(v.w - h3);
    }

    // ---- global softmax constant per row ----
    float M0 = -INFINITY, M1 = -INFINITY;
    #pragma unroll
    for (int n2 = 0; n2 < 8; ++n2) {
        M0 = fmaxf(M0, smem[O_MS + n2 * 64 + qr + gid]);
        M1 = fmaxf(M1, smem[O_MS + n2 * 64 + qr + gid + 8]);
    }
    float S0 = 0.f, S1 = 0.f;
    #pragma unroll
    for (int n2 = 0; n2 < 8; ++n2) {
        S0 += smem[O_SS + n2 * 64 + qr + gid]     * __expf(smem[O_MS + n2 * 64 + qr + gid]     - M0);
        S1 += smem[O_SS + n2 * 64 + qr + gid + 8] * __expf(smem[O_MS + n2 * 64 + qr + gid + 8] - M1);
    }
    const float Cr0 = M0 + __logf(S0);
    const float Cr1 = M1 + __logf(S1);
    __syncthreads();   // V tiles visible

    // ---- fused: p, attn store, P-frag shuffles, ctx mma ----
    float4 acc[8];
    #pragma unroll
    for (int nt = 0; nt < 8; ++nt) acc[nt] = make_float4(0.f, 0.f, 0.f, 0.f);

    #pragma unroll
    for (int f = 0; f < 5; ++f) {
        float p0 = __expf(C[f][0] - Cr0), p1 = __expf(C[f][1] - Cr0);
        float p2 = __expf(C[f][2] - Cr1), p3 = __expf(C[f][3] - Cr1);
        int k0 = klo + nb + f * 8 + 2 * tig;
        if (k0 < S_LEN) {
            *(float2*)(attn + (size_t)r0g       * S_LEN + k0) = make_float2(p0, p1);
            *(float2*)(attn + (size_t)(r0g + 8) * S_LEN + k0) = make_float2(p2, p3);
        }
        // A-fragments of P via shuffles: a0=P[gid][tig], a1=P[gid+8][tig], a2/a3 at tig+4
        int src1 = (gid << 2) + (tig >> 1);
        int src2 = src1 + 2;
        float q0a = __shfl_sync(0xffffffffu, p0, src1);
        float q1a = __shfl_sync(0xffffffffu, p1, src1);
        float q2a = __shfl_sync(0xffffffffu, p2, src1);
        float q3a = __shfl_sync(0xffffffffu, p3, src1);
        float q0b = __shfl_sync(0xffffffffu, p0, src2);
        float q1b = __shfl_sync(0xffffffffu, p1, src2);
        float q2b = __shfl_sync(0xffffffffu, p2, src2);
        float q3b = __shfl_sync(0xffffffffu, p3, src2);
        bool odd = (tig & 1);
        float a0f = odd ? q1a : q0a;
        float a1f = odd ? q3a : q2a;
        float a2f = odd ? q1b : q0b;
        float a3f = odd ? q3b : q2b;
        float h0f = tf32f(a0f), h1f = tf32f(a1f), h2f = tf32f(a2f), h3f = tf32f(a3f);
        uint32_t ah0 = __float_as_uint(h0f), ah1 = __float_as_uint(h1f);
        uint32_t ah2 = __float_as_uint(h2f), ah3 = __float_as_uint(h3f);
        uint32_t al0 = tf32c(a0f - h0f), al1 = tf32c(a1f - h1f);
        uint32_t al2 = tf32c(a2f - h2f), al3 = tf32c(a3f - h3f);

        const int kbase = nb + f * 8;
        const float* vh0 = smem + O_VH + (kbase + tig) * VP + gid;
        const float* vh1 = smem + O_VH + (kbase + tig + 4) * VP + gid;
        const float* vl0 = smem + O_VL + (kbase + tig) * VP + gid;
        const float* vl1 = smem + O_VL + (kbase + tig + 4) * VP + gid;
        #pragma unroll
        for (int nt = 0; nt < 8; ++nt) {
            uint32_t b0h = __float_as_uint(vh0[nt * 8]);
            uint32_t b1h = __float_as_uint(vh1[nt * 8]);
            uint32_t b0l = __float_as_uint(vl0[nt * 8]);
            uint32_t b1l = __float_as_uint(vl1[nt * 8]);
            mma8v(acc[nt], ah0, ah1, ah2, ah3, b0h, b1h);
            mma8v(acc[nt], al0, al1, al2, al3, b0h, b1h);
            mma8v(acc[nt], ah0, ah1, ah2, ah3, b0l, b1l);
        }
    }
    __syncthreads();   // all V reads done

    // ---- combine 8 nw partials (slots overlay V/K region) ----
    if (nw) {
        float4* slot = (float4*)smem + (m * 7 + nw - 1) * 256;
        #pragma unroll
        for (int i = 0; i < 8; ++i) slot[i * 32 + lane] = acc[i];
    }
    __syncthreads();
    if (!nw) {
        #pragma unroll
        for (int s = 0; s < 7; ++s) {
            const float4* slot = (const float4*)smem + (m * 7 + s) * 256;
            #pragma unroll
            for (int i = 0; i < 8; ++i) {
                float4 t = slot[i * 32 + lane];
                acc[i].x += t.x; acc[i].y += t.y; acc[i].z += t.z; acc[i].w += t.w;
            }
        }
        float* cb = ctx_out + ((size_t)bh * S_LEN + q0 + qr) * DH;
        #pragma unroll
        for (int nt = 0; nt < 8; ++nt) {
            int d0 = nt * 8 + 2 * tig;
            *(float2*)(cb + gid * DH + d0)       = make_float2(acc[nt].x, acc[nt].y);
            *(float2*)(cb + (gid + 8) * DH + d0) = make_float2(acc[nt].z, acc[nt].w);
        }
    }
}

extern "C" void kernel_launch(void* const* d_in, const int* in_sizes, int n_in,
                              void* d_out, int out_size)
{
    const float* Q = (const float*)d_in[0];
    const float* K = (const float*)d_in[1];
    const float* V = (const float*)d_in[2];

    float* out  = (float*)d_out;
    float* ctx  = out;                                 // [B,H,S,D] first
    float* attn = out + (size_t)NB * NH * S_LEN * DH;  // then [B,H,S,S]

    cudaFuncSetAttribute(band_attn_mma2,
                         cudaFuncAttributeMaxDynamicSharedMemorySize, SMEM_B);

    dim3 grid(S_LEN / TQ, NH, NB);
    band_attn_mma2<<<grid, NT, SMEM_B>>>(Q, K, V, ctx, attn);
}

// round 11
// speedup vs baseline: 1.4531x; 1.1969x over previous
#include <cuda_runtime.h>
#include <cuda_bf16.h>
#include <math.h>
#include <stdint.h>

#define S_LEN 2048
#define DH    64
#define NB    2
#define NH    8
#define WIN   128
#define TQ    32
#define NT    512
#define KW    320
#define SK    72     // K/Q row stride in u32: [hi 32][lo 32][pad 8]
#define SV    328    // Vt row stride in u32: [hi 160][lo 160][pad 8]

// u32 offsets
#define O_K   0        // K tile: 320*72 = 23040 u32 (Vt overlays later: 64*328=20992)
#define O_Q   23040    // Q tile: 32*72 = 2304
#define O_MS  25344    // f32 [8][32]
#define O_SS  25600
#define SM_U32 25856
#define SMEM_B (SM_U32 * 4)   // 103424 B -> 2 CTAs/SM

#define PERM(p) ((((p) & 3) << 1) | ((p) >> 2))
#define FI(f)   ((f) < 0 ? 0 : ((f) > 4 ? 4 : (f)))

__device__ __forceinline__ uint32_t pk(float x, float y) {
    __nv_bfloat162 h = __floats2bfloat162_rn(x, y);
    return *(uint32_t*)&h;
}
__device__ __forceinline__ uint32_t pkres(float x, float y, uint32_t h) {
    __nv_bfloat162 hh = *(__nv_bfloat162*)&h;
    return pk(x - __bfloat162float(hh.x), y - __bfloat162float(hh.y));
}
__device__ __forceinline__ void mmabf(float4& c, uint32_t a0, uint32_t a1, uint32_t a2,
                                      uint32_t a3, uint32_t b0, uint32_t b1) {
    asm("mma.sync.aligned.m16n8k16.row.col.f32.bf16.bf16.f32 "
        "{%0,%1,%2,%3}, {%4,%5,%6,%7}, {%8,%9}, {%0,%1,%2,%3};"
        : "+f"(c.x), "+f"(c.y), "+f"(c.z), "+f"(c.w)
        : "r"(a0), "r"(a1), "r"(a2), "r"(a3), "r"(b0), "r"(b1));
}

// GEMM2 k16 step: A = P frags (FA = low-half f, FB = high-half f; out of [0,4] -> zeros)
#define G2STEP(FA, FB, C2) do {                                                   \
    int ck = chunk0 + (C2);                                                       \
    if (ck * 16 + 15 >= glo && ck * 16 <= ghi) {                                  \
        uint32_t ah0, ah1, ah2, ah3, al0, al1, al2, al3;                          \
        if ((FA) >= 0) {                                                          \
            float4 pa = C[FI(FA)];                                                \
            ah0 = pk(pa.x, pa.y); al0 = pkres(pa.x, pa.y, ah0);                   \
            ah1 = pk(pa.z, pa.w); al1 = pkres(pa.z, pa.w, ah1);                   \
        } else { ah0 = ah1 = al0 = al1 = 0u; }                                    \
        if ((FB) <= 4) {                                                          \
            float4 pb = C[FI(FB)];                                                \
            ah2 = pk(pb.x, pb.y); al2 = pkres(pb.x, pb.y, ah2);                   \
            ah3 = pk(pb.z, pb.w); al3 = pkres(pb.z, pb.w, ah3);                   \
        } else { ah2 = ah3 = al2 = al3 = 0u; }                                    \
        int ch8 = ck * 8;                                                         \
        _Pragma("unroll")                                                         \
        for (int nt = 0; nt < 8; ++nt) {                                          \
            uint32_t dr = nt * 8 + gid;                                           \
            uint32_t bi = dr * SV + ch8 + ((2u * tig) ^ (((dr >> 2) & 3u) << 1)); \
            uint2 bhv = *(const uint2*)(su + bi);                                 \
            uint2 blv = *(const uint2*)(su + bi + 160);                           \
            mmabf(acc[nt], ah0, ah1, ah2, ah3, bhv.x, bhv.y);                     \
            mmabf(acc[nt], al0, al1, al2, al3, bhv.x, bhv.y);                     \
            mmabf(acc[nt], ah0, ah1, ah2, ah3, blv.x, blv.y);                     \
        }                                                                         \
    }                                                                             \
} while (0)

__global__ void __launch_bounds__(NT, 2)
band_attn_bf16(const float* __restrict__ Q, const float* __restrict__ K,
               const float* __restrict__ V, float* __restrict__ ctx_out,
               float* __restrict__ attn_out)
{
    extern __shared__ float smem[];
    uint32_t* su = (uint32_t*)smem;
    float*    sf = smem;

    const int tid = threadIdx.x, w = tid >> 5, lane = tid & 31;
    const int gid = lane >> 2, tig = lane & 3;
    const int m = w >> 3, nw = w & 7;          // 2 row-groups x 8 col-groups
    const int bh = blockIdx.z * NH + blockIdx.y;
    const int q0 = blockIdx.x * TQ;
    const int klo = max(0, q0 - 128);
    const int khi = min(S_LEN - 1, q0 + TQ - 1 + WIN - 1);
    const int cnt = khi - klo + 1;             // <= 287

    const float* Qg = Q + (size_t)bh * S_LEN * DH;
    const float* Kg = K + (size_t)bh * S_LEN * DH;
    const float* Vg = V + (size_t)bh * S_LEN * DH;
    float* attn = attn_out + (size_t)bh * S_LEN * S_LEN;

    // ---- K tile: bf16 hi/lo, permuted pair layout ----
    for (int i = tid; i < cnt * 16; i += NT) {
        int r = i >> 4, dq = i & 15;
        float4 v = ((const float4*)Kg)[(klo + r) * 16 + dq];
        int c = dq >> 2;
        int u0 = PERM((2 * dq) & 7), u1 = PERM((2 * dq + 1) & 7);
        uint32_t base = O_K + r * SK + c * 8;
        uint32_t h0 = pk(v.x, v.y), h1 = pk(v.z, v.w);
        su[base + u0] = h0;            su[base + u1] = h1;
        su[base + 32 + u0] = pkres(v.x, v.y, h0);
        su[base + 32 + u1] = pkres(v.z, v.w, h1);
    }
    // ---- Q tile: scale 1/8, same layout ----
    {
        int i = tid;                    // 32*16 = 512 items, one per thread
        int r = i >> 4, dq = i & 15;
        float4 v = ((const float4*)Qg)[(q0 + r) * 16 + dq];
        float x0 = v.x * 0.125f, x1 = v.y * 0.125f, x2 = v.z * 0.125f, x3 = v.w * 0.125f;
        int c = dq >> 2;
        int u0 = PERM((2 * dq) & 7), u1 = PERM((2 * dq + 1) & 7);
        uint32_t base = O_Q + r * SK + c * 8;
        uint32_t h0 = pk(x0, x1), h1 = pk(x2, x3);
        su[base + u0] = h0;            su[base + u1] = h1;
        su[base + 32 + u0] = pkres(x0, x1, h0);
        su[base + 32 + u1] = pkres(x2, x3, h1);
    }
    // ---- zero-fill attn outside the 320-wide strip ----
    {
        float* t0 = attn + (size_t)q0 * S_LEN;
        if (4 * tid + 3 < klo || 4 * tid >= klo + KW) {
            const float4 z4 = make_float4(0.f, 0.f, 0.f, 0.f);
            #pragma unroll 8
            for (int r = 0; r < TQ; ++r)
                ((float4*)(t0 + (size_t)r * S_LEN))[tid] = z4;
        }
    }
    __syncthreads();

    // ---- warp geometry ----
    const int qr = m * 16, nb = nw * 40;
    const int glo = max(0, q0 + qr - 127) - klo;
    const int ghi = min(S_LEN - 1, q0 + qr + 15 + 127) - klo;
    bool alive[5];
    #pragma unroll
    for (int f = 0; f < 5; ++f)
        alive[f] = (nb + 8 * f + 7 >= glo) && (nb + 8 * f <= ghi);

    // ---- GEMM1: C[32x320] = Qs . K^T (bf16 3-term) ----
    float4 C[5];
    #pragma unroll
    for (int f = 0; f < 5; ++f) C[f] = make_float4(0.f, 0.f, 0.f, 0.f);

    #pragma unroll
    for (int ks = 0; ks < 4; ++ks) {
        uint32_t qa = O_Q + (qr + gid) * SK + ks * 8 + 2 * tig;
        uint32_t qb = O_Q + (qr + gid + 8) * SK + ks * 8 + 2 * tig;
        uint2 qh0 = *(const uint2*)(su + qa);
        uint2 qh1 = *(const uint2*)(su + qb);
        uint2 ql0 = *(const uint2*)(su + qa + 32);
        uint2 ql1 = *(const uint2*)(su + qb + 32);
        #pragma unroll
        for (int f = 0; f < 5; ++f) {
            if (!alive[f]) continue;
            uint32_t kb = O_K + (nb + 8 * f + gid) * SK + ks * 8 + 2 * tig;
            uint2 bhv = *(const uint2*)(su + kb);
            uint2 blv = *(const uint2*)(su + kb + 32);
            mmabf(C[f], qh0.x, qh1.x, qh0.y, qh1.y, bhv.x, bhv.y);
            mmabf(C[f], ql0.x, ql1.x, ql0.y, ql1.y, bhv.x, bhv.y);
            mmabf(C[f], qh0.x, qh1.x, qh0.y, qh1.y, blv.x, blv.y);
        }
    }

    // ---- band mask + local row stats ----
    const int r0g = q0 + qr + gid;
    float mr0 = -INFINITY, mr1 = -INFINITY;
    #pragma unroll
    for (int f = 0; f < 5; ++f) {
        int k0 = klo + nb + 8 * f + 2 * tig;
        bool v0 = (unsigned)(r0g     - k0     + WIN - 1) <= 2 * (WIN - 1) && k0     <= khi;
        bool v1 = (unsigned)(r0g     - k0 - 1 + WIN - 1) <= 2 * (WIN - 1) && k0 + 1 <= khi;
        bool v2 = (unsigned)(r0g + 8 - k0     + WIN - 1) <= 2 * (WIN - 1) && k0     <= khi;
        bool v3 = (unsigned)(r0g + 8 - k0 - 1 + WIN - 1) <= 2 * (WIN - 1) && k0 + 1 <= khi;
        C[f].x = v0 ? C[f].x : -INFINITY;
        C[f].y = v1 ? C[f].y : -INFINITY;
        C[f].z = v2 ? C[f].z : -INFINITY;
        C[f].w = v3 ? C[f].w : -INFINITY;
        mr0 = fmaxf(mr0, fmaxf(C[f].x, C[f].y));
        mr1 = fmaxf(mr1, fmaxf(C[f].z, C[f].w));
    }
    #pragma unroll
    for (int off = 1; off <= 2; off <<= 1) {
        mr0 = fmaxf(mr0, __shfl_xor_sync(0xffffffffu, mr0, off));
        mr1 = fmaxf(mr1, __shfl_xor_sync(0xffffffffu, mr1, off));
    }
    mr0 = fmaxf(mr0, -1e30f); mr1 = fmaxf(mr1, -1e30f);
    float sr0 = 0.f, sr1 = 0.f;
    #pragma unroll
    for (int f = 0; f < 5; ++f) {
        sr0 += __expf(C[f].x - mr0) + __expf(C[f].y - mr0);
        sr1 += __expf(C[f].z - mr1) + __expf(C[f].w - mr1);
    }
    #pragma unroll
    for (int off = 1; off <= 2; off <<= 1) {
        sr0 += __shfl_xor_sync(0xffffffffu, sr0, off);
        sr1 += __shfl_xor_sync(0xffffffffu, sr1, off);
    }
    if (tig == 0) {
        sf[O_MS + nw * 32 + qr + gid]     = mr0;  sf[O_SS + nw * 32 + qr + gid]     = sr0;
        sf[O_MS + nw * 32 + qr + gid + 8] = mr1;  sf[O_SS + nw * 32 + qr + gid + 8] = sr1;
    }
    __syncthreads();   // K dead; stats visible

    // ---- Vt convert into K region: bf16 hi/lo, key-pairs packed, transposed ----
    for (int i = tid; i < 160 * 16; i += NT) {
        int kp = i >> 4, dq = i & 15;
        int r0 = 2 * kp, r1 = 2 * kp + 1;
        float4 v0 = (r0 < cnt) ? ((const float4*)Vg)[(klo + r0) * 16 + dq]
                               : make_float4(0.f, 0.f, 0.f, 0.f);
        float4 v1 = (r1 < cnt) ? ((const float4*)Vg)[(klo + r1) * 16 + dq]
                               : make_float4(0.f, 0.f, 0.f, 0.f);
        int c16 = kp >> 3, u = PERM(kp & 7);
        #pragma unroll
        for (int j = 0; j < 4; ++j) {
            float x0 = (j == 0) ? v0.x : (j == 1) ? v0.y : (j == 2) ? v0.z : v0.w;
            float x1 = (j == 0) ? v1.x : (j == 1) ? v1.y : (j == 2) ? v1.z : v1.w;
            int d = 4 * dq + j;
            uint32_t idx = d * SV + c16 * 8 + (u ^ (((d >> 2) & 3) << 1));
            uint32_t h = pk(x0, x1);
            su[idx] = h;
            su[idx + 160] = pkres(x0, x1, h);
        }
    }

    // ---- global softmax constant per row ----
    float M0 = -INFINITY, M1 = -INFINITY;
    #pragma unroll
    for (int n2 = 0; n2 < 8; ++n2) {
        M0 = fmaxf(M0, sf[O_MS + n2 * 32 + qr + gid]);
        M1 = fmaxf(M1, sf[O_MS + n2 * 32 + qr + gid + 8]);
    }
    float S0 = 0.f, S1 = 0.f;
    #pragma unroll
    for (int n2 = 0; n2 < 8; ++n2) {
        S0 += sf[O_SS + n2 * 32 + qr + gid]     * __expf(sf[O_MS + n2 * 32 + qr + gid]     - M0);
        S1 += sf[O_SS + n2 * 32 + qr + gid + 8] * __expf(sf[O_MS + n2 * 32 + qr + gid + 8] - M1);
    }
    const float Cr0 = M0 + __logf(S0);
    const float Cr1 = M1 + __logf(S1);
    __syncthreads();   // Vt ready

    // ---- p = exp(C - Cr), attn band stores (C overwritten with p) ----
    #pragma unroll
    for (int f = 0; f < 5; ++f) {
        float p0 = __expf(C[f].x - Cr0), p1 = __expf(C[f].y - Cr0);
        float p2 = __expf(C[f].z - Cr1), p3 = __expf(C[f].w - Cr1);
        C[f] = make_float4(p0, p1, p2, p3);
        int k0 = klo + nb + 8 * f + 2 * tig;
        if (k0 < S_LEN) {
            *(float2*)(attn + (size_t)r0g       * S_LEN + k0) = make_float2(p0, p1);
            *(float2*)(attn + (size_t)(r0g + 8) * S_LEN + k0) = make_float2(p2, p3);
        }
    }

    // ---- GEMM2: ctx = P . V (bf16 3-term, k16 from C-frag pairs) ----
    float4 acc[8];
    #pragma unroll
    for (int nt = 0; nt < 8; ++nt) acc[nt] = make_float4(0.f, 0.f, 0.f, 0.f);
    const int chunk0 = (nb - 8 * (nw & 1)) >> 4;
    if (!(nw & 1)) { G2STEP(0, 1, 0); G2STEP(2, 3, 1); G2STEP(4, 5, 2); }
    else           { G2STEP(-1, 0, 0); G2STEP(1, 2, 1); G2STEP(3, 4, 2); }
    __syncthreads();   // Vt dead

    // ---- combine 8 nw partials (slots overlay Vt/K region) ----
    if (nw) {
        float4* sp = (float4*)sf + (m * 7 + nw - 1) * 256;
        #pragma unroll
        for (int nt = 0; nt < 8; ++nt) sp[nt * 32 + lane] = acc[nt];
    }
    __syncthreads();
    if (!nw) {
        #pragma unroll
        for (int s = 0; s < 7; ++s) {
            const float4* sp = (const float4*)sf + (m * 7 + s) * 256;
            #pragma unroll
            for (int nt = 0; nt < 8; ++nt) {
                float4 t = sp[nt * 32 + lane];
                acc[nt].x += t.x; acc[nt].y += t.y; acc[nt].z += t.z; acc[nt].w += t.w;
            }
        }
        float* cb = ctx_out + ((size_t)bh * S_LEN + q0 + qr) * DH;
        #pragma unroll
        for (int nt = 0; nt < 8; ++nt) {
            int d0 = nt * 8 + 2 * tig;
            *(float2*)(cb + gid * DH + d0)       = make_float2(acc[nt].x, acc[nt].y);
            *(float2*)(cb + (gid + 8) * DH + d0) = make_float2(acc[nt].z, acc[nt].w);
        }
    }
}

extern "C" void kernel_launch(void* const* d_in, const int* in_sizes, int n_in,
                              void* d_out, int out_size)
{
    const float* Q = (const float*)d_in[0];
    const float* K = (const float*)d_in[1];
    const float* V = (const float*)d_in[2];

    float* out  = (float*)d_out;
    float* ctx  = out;                                 // [B,H,S,D] first
    float* attn = out + (size_t)NB * NH * S_LEN * DH;  // then [B,H,S,S]

    cudaFuncSetAttribute(band_attn_bf16,
                         cudaFuncAttributeMaxDynamicSharedMemorySize, SMEM_B);

    dim3 grid(S_LEN / TQ, NH, NB);
    band_attn_bf16<<<grid, NT, SMEM_B>>>(Q, K, V, ctx, attn);
}

// round 12
// speedup vs baseline: 1.5002x; 1.0324x over previous
#include <cuda_runtime.h>
#include <cuda_bf16.h>
#include <math.h>
#include <stdint.h>

#define S_LEN 2048
#define DH    64
#define NB    2
#define NH    8
#define WIN   128
#define TQ    32
#define NT    512
#define KW    320
#define SK    72     // K/Q smem row stride (u32): [hi 32][lo 32][pad 8]
#define SV    328    // Vt smem row stride (u32): [hi 160][lo 160][pad 8]
#define VROW  1104   // Vt gmem row stride (u32), padded (max klo2+160 = 1104)

// u32 smem offsets
#define O_K   0        // K tile 320*72 = 23040 (Vt overlays later: 64*328 = 20992)
#define O_Q   23040    // Q tile 32*72 = 2304
#define O_MS  25344    // f32 [8][32]
#define O_SS  25600
#define SM_U32 25856
#define SMEM_B (SM_U32 * 4)   // 103424 B -> 2 CTAs/SM

#define PERM(p) ((((p) & 3) << 1) | ((p) >> 2))
#define FI(f)   ((f) < 0 ? 0 : ((f) > 4 ? 4 : (f)))

// pre-converted tiles (zero-initialized statics; ~25 MB)
__device__ uint32_t d_Kp[NB * NH * S_LEN * 64];
__device__ uint32_t d_Qp[NB * NH * S_LEN * 64];
__device__ uint32_t d_Vh[NB * NH * DH * VROW];
__device__ uint32_t d_Vl[NB * NH * DH * VROW];

__device__ __forceinline__ uint32_t pk(float x, float y) {
    __nv_bfloat162 h = __floats2bfloat162_rn(x, y);
    return *(uint32_t*)&h;
}
__device__ __forceinline__ uint32_t pkres(float x, float y, uint32_t h) {
    __nv_bfloat162 hh = *(__nv_bfloat162*)&h;
    return pk(x - __bfloat162float(hh.x), y - __bfloat162float(hh.y));
}
__device__ __forceinline__ void mmabf(float4& c, uint32_t a0, uint32_t a1, uint32_t a2,
                                      uint32_t a3, uint32_t b0, uint32_t b1) {
    asm("mma.sync.aligned.m16n8k16.row.col.f32.bf16.bf16.f32 "
        "{%0,%1,%2,%3}, {%4,%5,%6,%7}, {%8,%9}, {%0,%1,%2,%3};"
        : "+f"(c.x), "+f"(c.y), "+f"(c.z), "+f"(c.w)
        : "r"(a0), "r"(a1), "r"(a2), "r"(a3), "r"(b0), "r"(b1));
}

// ---- prep: convert K/Q/V once, in final layouts ----
__global__ void __launch_bounds__(256)
prep_kernel(const float* __restrict__ Q, const float* __restrict__ K,
            const float* __restrict__ V)
{
    int idx = blockIdx.x * blockDim.x + threadIdx.x;     // 524288 total
    {   // K + Q rows: (bh, r, dq)
        int dq = idx & 15, r = (idx >> 4) & (S_LEN - 1), bh = idx >> 15;
        int c = dq >> 2;
        int u0 = PERM((2 * dq) & 7), u1 = PERM((2 * dq + 1) & 7);
        size_t rowi = (size_t)(bh * S_LEN + r);
        float4 kv = ((const float4*)K)[rowi * 16 + dq];
        uint32_t* kr = d_Kp + rowi * 64 + c * 8;
        uint32_t h0 = pk(kv.x, kv.y), h1 = pk(kv.z, kv.w);
        kr[u0] = h0; kr[u1] = h1;
        kr[32 + u0] = pkres(kv.x, kv.y, h0);
        kr[32 + u1] = pkres(kv.z, kv.w, h1);
        float4 qv = ((const float4*)Q)[rowi * 16 + dq];
        float x0 = qv.x * 0.125f, x1 = qv.y * 0.125f, x2 = qv.z * 0.125f, x3 = qv.w * 0.125f;
        uint32_t* qr = d_Qp + rowi * 64 + c * 8;
        uint32_t g0 = pk(x0, x1), g1 = pk(x2, x3);
        qr[u0] = g0; qr[u1] = g1;
        qr[32 + u0] = pkres(x0, x1, g0);
        qr[32 + u1] = pkres(x2, x3, g1);
    }
    if (idx < NB * NH * 16 * 1024) {   // V transpose: (bh, dq, kp), kp innermost
        int kp = idx & 1023, dq = (idx >> 10) & 15, bh = idx >> 14;
        float4 v0 = ((const float4*)V)[((size_t)(bh * S_LEN) + 2 * kp) * 16 + dq];
        float4 v1 = ((const float4*)V)[((size_t)(bh * S_LEN) + 2 * kp + 1) * 16 + dq];
        int cc = (kp >> 3) * 8, uu = PERM(kp & 7);
        #pragma unroll
        for (int j = 0; j < 4; ++j) {
            float x0 = (j == 0) ? v0.x : (j == 1) ? v0.y : (j == 2) ? v0.z : v0.w;
            float x1 = (j == 0) ? v1.x : (j == 1) ? v1.y : (j == 2) ? v1.z : v1.w;
            int d = 4 * dq + j;
            uint32_t o = (uint32_t)(bh * DH + d) * VROW + cc + (uu ^ (((d >> 2) & 3) << 1));
            uint32_t h = pk(x0, x1);
            d_Vh[o] = h;
            d_Vl[o] = pkres(x0, x1, h);
        }
    }
}

// GEMM2 k16 step (A = P frags; FA/FB outside [0,4] -> zeros)
#define G2STEP(FA, FB, C2) do {                                                   \
    int ck = chunk0 + (C2);                                                       \
    if (ck * 16 + 15 >= glo && ck * 16 <= ghi) {                                  \
        uint32_t ah0, ah1, ah2, ah3, al0, al1, al2, al3;                          \
        if ((FA) >= 0) {                                                          \
            float4 pa = C[FI(FA)];                                                \
            ah0 = pk(pa.x, pa.y); al0 = pkres(pa.x, pa.y, ah0);                   \
            ah1 = pk(pa.z, pa.w); al1 = pkres(pa.z, pa.w, ah1);                   \
        } else { ah0 = ah1 = al0 = al1 = 0u; }                                    \
        if ((FB) <= 4) {                                                          \
            float4 pb = C[FI(FB)];                                                \
            ah2 = pk(pb.x, pb.y); al2 = pkres(pb.x, pb.y, ah2);                   \
            ah3 = pk(pb.z, pb.w); al3 = pkres(pb.z, pb.w, ah3);                   \
        } else { ah2 = ah3 = al2 = al3 = 0u; }                                    \
        int ch8 = ck * 8;                                                         \
        _Pragma("unroll")                                                         \
        for (int nt = 0; nt < 8; ++nt) {                                          \
            uint32_t dr = nt * 8 + gid;                                           \
            uint32_t bi = dr * SV + ch8 + ((2u * tig) ^ (((dr >> 2) & 3u) << 1)); \
            uint2 bhv = *(const uint2*)(su + bi);                                 \
            uint2 blv = *(const uint2*)(su + bi + 160);                           \
            mmabf(acc[nt], ah0, ah1, ah2, ah3, bhv.x, bhv.y);                     \
            mmabf(acc[nt], al0, al1, al2, al3, bhv.x, bhv.y);                     \
            mmabf(acc[nt], ah0, ah1, ah2, ah3, blv.x, blv.y);                     \
        }                                                                         \
    }                                                                             \
} while (0)

__global__ void __launch_bounds__(NT, 2)
band_attn_bf16(const float* __restrict__ Q, const float* __restrict__ K,
               const float* __restrict__ V, float* __restrict__ ctx_out,
               float* __restrict__ attn_out)
{
    extern __shared__ float smem[];
    uint32_t* su = (uint32_t*)smem;
    float*    sf = smem;

    const int tid = threadIdx.x, w = tid >> 5, lane = tid & 31;
    const int gid = lane >> 2, tig = lane & 3;
    const int m = w >> 3, nw = w & 7;
    const int bh = blockIdx.z * NH + blockIdx.y;
    const int q0 = blockIdx.x * TQ;
    const int klo = max(0, q0 - 128);
    const int klo2 = klo >> 1;                 // multiple of 16
    const int khi = min(S_LEN - 1, q0 + TQ - 1 + WIN - 1);
    const int cnt = khi - klo + 1;             // <= 287

    float* attn = attn_out + (size_t)bh * S_LEN * S_LEN;

    // ---- K tile: straight uint4 copy of pre-converted rows ----
    for (int i = tid; i < cnt * 16; i += NT) {
        int r = i >> 4, c = i & 15;
        ((uint4*)(su + O_K + r * SK))[c] =
            ((const uint4*)(d_Kp + ((size_t)(bh * S_LEN) + klo + r) * 64))[c];
    }
    // ---- Q tile copy (512 uint4, one per thread) ----
    {
        int r = tid >> 4, c = tid & 15;
        ((uint4*)(su + O_Q + r * SK))[c] =
            ((const uint4*)(d_Qp + ((size_t)(bh * S_LEN) + q0 + r) * 64))[c];
    }
    // ---- zero-fill attn outside the 320-wide strip ----
    {
        float* t0 = attn + (size_t)q0 * S_LEN;
        if (4 * tid + 3 < klo || 4 * tid >= klo + KW) {
            const float4 z4 = make_float4(0.f, 0.f, 0.f, 0.f);
            #pragma unroll 8
            for (int r = 0; r < TQ; ++r)
                ((float4*)(t0 + (size_t)r * S_LEN))[tid] = z4;
        }
    }
    __syncthreads();

    // ---- warp geometry ----
    const int qr = m * 16, nb = nw * 40;
    const int glo = max(0, q0 + qr - 127) - klo;
    const int ghi = min(S_LEN - 1, q0 + qr + 15 + 127) - klo;
    bool alive[5];
    #pragma unroll
    for (int f = 0; f < 5; ++f)
        alive[f] = (nb + 8 * f + 7 >= glo) && (nb + 8 * f <= ghi);

    // ---- GEMM1: C[32x320] = Qs . K^T (bf16 3-term) ----
    float4 C[5];
    #pragma unroll
    for (int f = 0; f < 5; ++f) C[f] = make_float4(0.f, 0.f, 0.f, 0.f);

    #pragma unroll
    for (int ks = 0; ks < 4; ++ks) {
        uint32_t qa = O_Q + (qr + gid) * SK + ks * 8 + 2 * tig;
        uint32_t qb = O_Q + (qr + gid + 8) * SK + ks * 8 + 2 * tig;
        uint2 qh0 = *(const uint2*)(su + qa);
        uint2 qh1 = *(const uint2*)(su + qb);
        uint2 ql0 = *(const uint2*)(su + qa + 32);
        uint2 ql1 = *(const uint2*)(su + qb + 32);
        #pragma unroll
        for (int f = 0; f < 5; ++f) {
            if (!alive[f]) continue;
            uint32_t kb = O_K + (nb + 8 * f + gid) * SK + ks * 8 + 2 * tig;
            uint2 bhv = *(const uint2*)(su + kb);
            uint2 blv = *(const uint2*)(su + kb + 32);
            mmabf(C[f], qh0.x, qh1.x, qh0.y, qh1.y, bhv.x, bhv.y);
            mmabf(C[f], ql0.x, ql1.x, ql0.y, ql1.y, bhv.x, bhv.y);
            mmabf(C[f], qh0.x, qh1.x, qh0.y, qh1.y, blv.x, blv.y);
        }
    }

    // ---- band mask + local row stats ----
    const int r0g = q0 + qr + gid;
    float mr0 = -INFINITY, mr1 = -INFINITY;
    #pragma unroll
    for (int f = 0; f < 5; ++f) {
        int k0 = klo + nb + 8 * f + 2 * tig;
        bool v0 = (unsigned)(r0g     - k0     + WIN - 1) <= 2 * (WIN - 1) && k0     <= khi;
        bool v1 = (unsigned)(r0g     - k0 - 1 + WIN - 1) <= 2 * (WIN - 1) && k0 + 1 <= khi;
        bool v2 = (unsigned)(r0g + 8 - k0     + WIN - 1) <= 2 * (WIN - 1) && k0     <= khi;
        bool v3 = (unsigned)(r0g + 8 - k0 - 1 + WIN - 1) <= 2 * (WIN - 1) && k0 + 1 <= khi;
        C[f].x = v0 ? C[f].x : -INFINITY;
        C[f].y = v1 ? C[f].y : -INFINITY;
        C[f].z = v2 ? C[f].z : -INFINITY;
        C[f].w = v3 ? C[f].w : -INFINITY;
        mr0 = fmaxf(mr0, fmaxf(C[f].x, C[f].y));
        mr1 = fmaxf(mr1, fmaxf(C[f].z, C[f].w));
    }
    #pragma unroll
    for (int off = 1; off <= 2; off <<= 1) {
        mr0 = fmaxf(mr0, __shfl_xor_sync(0xffffffffu, mr0, off));
        mr1 = fmaxf(mr1, __shfl_xor_sync(0xffffffffu, mr1, off));
    }
    mr0 = fmaxf(mr0, -1e30f); mr1 = fmaxf(mr1, -1e30f);
    float sr0 = 0.f, sr1 = 0.f;
    #pragma unroll
    for (int f = 0; f < 5; ++f) {
        sr0 += __expf(C[f].x - mr0) + __expf(C[f].y - mr0);
        sr1 += __expf(C[f].z - mr1) + __expf(C[f].w - mr1);
    }
    #pragma unroll
    for (int off = 1; off <= 2; off <<= 1) {
        sr0 += __shfl_xor_sync(0xffffffffu, sr0, off);
        sr1 += __shfl_xor_sync(0xffffffffu, sr1, off);
    }
    if (tig == 0) {
        sf[O_MS + nw * 32 + qr + gid]     = mr0;  sf[O_SS + nw * 32 + qr + gid]     = sr0;
        sf[O_MS + nw * 32 + qr + gid + 8] = mr1;  sf[O_SS + nw * 32 + qr + gid + 8] = sr1;
    }
    __syncthreads();   // K dead; stats visible

    // ---- Vt copy into K region (pure uint4 copies, swizzle pre-baked) ----
    for (int i = tid; i < 64 * 40; i += NT) {
        int d = i / 40, c = i - d * 40;
        size_t gb = (size_t)(bh * DH + d) * VROW + klo2;
        ((uint4*)(su + d * SV))[c]       = ((const uint4*)(d_Vh + gb))[c];
        ((uint4*)(su + d * SV + 160))[c] = ((const uint4*)(d_Vl + gb))[c];
    }

    // ---- global softmax constant per row ----
    float M0 = -INFINITY, M1 = -INFINITY;
    #pragma unroll
    for (int n2 = 0; n2 < 8; ++n2) {
        M0 = fmaxf(M0, sf[O_MS + n2 * 32 + qr + gid]);
        M1 = fmaxf(M1, sf[O_MS + n2 * 32 + qr + gid + 8]);
    }
    float S0 = 0.f, S1 = 0.f;
    #pragma unroll
    for (int n2 = 0; n2 < 8; ++n2) {
        S0 += sf[O_SS + n2 * 32 + qr + gid]     * __expf(sf[O_MS + n2 * 32 + qr + gid]     - M0);
        S1 += sf[O_SS + n2 * 32 + qr + gid + 8] * __expf(sf[O_MS + n2 * 32 + qr + gid + 8] - M1);
    }
    const float Cr0 = M0 + __logf(S0);
    const float Cr1 = M1 + __logf(S1);
    __syncthreads();   // Vt ready

    // ---- p = exp(C - Cr), attn band stores ----
    #pragma unroll
    for (int f = 0; f < 5; ++f) {
        float p0 = __expf(C[f].x - Cr0), p1 = __expf(C[f].y - Cr0);
        float p2 = __expf(C[f].z - Cr1), p3 = __expf(C[f].w - Cr1);
        C[f] = make_float4(p0, p1, p2, p3);
        int k0 = klo + nb + 8 * f + 2 * tig;
        if (k0 < S_LEN) {
            *(float2*)(attn + (size_t)r0g       * S_LEN + k0) = make_float2(p0, p1);
            *(float2*)(attn + (size_t)(r0g + 8) * S_LEN + k0) = make_float2(p2, p3);
        }
    }

    // ---- GEMM2: ctx = P . V ----
    float4 acc[8];
    #pragma unroll
    for (int nt = 0; nt < 8; ++nt) acc[nt] = make_float4(0.f, 0.f, 0.f, 0.f);
    const int chunk0 = (nb - 8 * (nw & 1)) >> 4;
    if (!(nw & 1)) { G2STEP(0, 1, 0); G2STEP(2, 3, 1); G2STEP(4, 5, 2); }
    else           { G2STEP(-1, 0, 0); G2STEP(1, 2, 1); G2STEP(3, 4, 2); }
    __syncthreads();   // Vt dead

    // ---- combine 8 nw partials ----
    if (nw) {
        float4* sp = (float4*)sf + (m * 7 + nw - 1) * 256;
        #pragma unroll
        for (int nt = 0; nt < 8; ++nt) sp[nt * 32 + lane] = acc[nt];
    }
    __syncthreads();
    if (!nw) {
        #pragma unroll
        for (int s = 0; s < 7; ++s) {
            const float4* sp = (const float4*)sf + (m * 7 + s) * 256;
            #pragma unroll
            for (int nt = 0; nt < 8; ++nt) {
                float4 t = sp[nt * 32 + lane];
                acc[nt].x += t.x; acc[nt].y += t.y; acc[nt].z += t.z; acc[nt].w += t.w;
            }
        }
        float* cb = ctx_out + ((size_t)bh * S_LEN + q0 + qr) * DH;
        #pragma unroll
        for (int nt = 0; nt < 8; ++nt) {
            int d0 = nt * 8 + 2 * tig;
            *(float2*)(cb + gid * DH + d0)       = make_float2(acc[nt].x, acc[nt].y);
            *(float2*)(cb + (gid + 8) * DH + d0) = make_float2(acc[nt].z, acc[nt].w);
        }
    }
}

extern "C" void kernel_launch(void* const* d_in, const int* in_sizes, int n_in,
                              void* d_out, int out_size)
{
    const float* Q = (const float*)d_in[0];
    const float* K = (const float*)d_in[1];
    const float* V = (const float*)d_in[2];

    float* out  = (float*)d_out;
    float* ctx  = out;                                 // [B,H,S,D] first
    float* attn = out + (size_t)NB * NH * S_LEN * DH;  // then [B,H,S,S]

    prep_kernel<<<(NB * NH * S_LEN * 16) / 256, 256>>>(Q, K, V);

    cudaFuncSetAttribute(band_attn_bf16,
                         cudaFuncAttributeMaxDynamicSharedMemorySize, SMEM_B);
    dim3 grid(S_LEN / TQ, NH, NB);
    band_attn_bf16<<<grid, NT, SMEM_B>>>(Q, K, V, ctx, attn);
}

// round 13
// speedup vs baseline: 1.5739x; 1.0492x over previous
#include <cuda_runtime.h>
#include <cuda_bf16.h>
#include <math.h>
#include <stdint.h>

#define S_LEN 2048
#define DH    64
#define NB    2
#define NH    8
#define WIN   128
#define TQ    32
#define NT    512
#define KW    320
#define SK    80     // K/Q smem row stride (u32); 320B ≡ 64 mod 128 -> LDS.128 conflict-free
#define SV    336    // Vt smem row stride (u32); 1344B ≡ 64 mod 128
#define VROW  2208   // Vt gmem row stride (u32): covers klo2*2+320 at max klo2=944

// u32 smem offsets
#define O_K   0        // K tile 320*80 = 25600 (Vt overlay 64*336 = 21504; slots 14336)
#define O_Q   25600    // Q tile 32*80 = 2560
#define O_MS  28160    // f32 [8][32]
#define O_SS  28416
#define SM_U32 28672
#define SMEM_B (SM_U32 * 4)   // 114688 B -> 2 CTAs/SM (229376 <= 232448)

#define PERM(p) ((((p) & 3) << 1) | ((p) >> 2))
#define FI(f)   ((f) < 0 ? 0 : ((f) > 4 ? 4 : (f)))

// pre-converted tiles (static zero-init; ~17 MB)
__device__ uint32_t d_Kp[NB * NH * S_LEN * 64];
__device__ uint32_t d_Vt[NB * NH * DH * VROW];

__device__ __forceinline__ uint32_t pk(float x, float y) {
    __nv_bfloat162 h = __floats2bfloat162_rn(x, y);
    return *(uint32_t*)&h;
}
__device__ __forceinline__ uint32_t pkres(float x, float y, uint32_t h) {
    __nv_bfloat162 hh = *(__nv_bfloat162*)&h;
    return pk(x - __bfloat162float(hh.x), y - __bfloat162float(hh.y));
}
__device__ __forceinline__ void mmabf(float4& c, uint32_t a0, uint32_t a1, uint32_t a2,
                                      uint32_t a3, uint32_t b0, uint32_t b1) {
    asm("mma.sync.aligned.m16n8k16.row.col.f32.bf16.bf16.f32 "
        "{%0,%1,%2,%3}, {%4,%5,%6,%7}, {%8,%9}, {%0,%1,%2,%3};"
        : "+f"(c.x), "+f"(c.y), "+f"(c.z), "+f"(c.w)
        : "r"(a0), "r"(a1), "r"(a2), "r"(a3), "r"(b0), "r"(b1));
}

// ---- prep: convert K and V once, hi/lo interleaved final layouts ----
__global__ void __launch_bounds__(256)
prep_kernel(const float* __restrict__ K, const float* __restrict__ V)
{
    int idx = blockIdx.x * blockDim.x + threadIdx.x;     // 524288
    {   // K rows: (bh, r, dq)
        int dq = idx & 15, r = (idx >> 4) & (S_LEN - 1), bh = idx >> 15;
        int ks = dq >> 2;
        int p0 = PERM((2 * dq) & 7), p1 = PERM((2 * dq + 1) & 7);
        size_t rowi = (size_t)(bh * S_LEN + r);
        float4 kv = ((const float4*)K)[rowi * 16 + dq];
        uint32_t* kr = d_Kp + rowi * 64;
        uint32_t h0 = pk(kv.x, kv.y), h1 = pk(kv.z, kv.w);
        int o0 = ks * 16 + ((p0 >> 1) << 2) + (p0 & 1);
        int o1 = ks * 16 + ((p1 >> 1) << 2) + (p1 & 1);
        kr[o0] = h0; kr[o0 + 2] = pkres(kv.x, kv.y, h0);
        kr[o1] = h1; kr[o1 + 2] = pkres(kv.z, kv.w, h1);
    }
    if (idx < NB * NH * 16 * 1024) {   // V transpose: (bh, dq, kp)
        int kp = idx & 1023, dq = (idx >> 10) & 15, bh = idx >> 14;
        float4 v0 = ((const float4*)V)[((size_t)(bh * S_LEN) + 2 * kp) * 16 + dq];
        float4 v1 = ((const float4*)V)[((size_t)(bh * S_LEN) + 2 * kp + 1) * 16 + dq];
        int ch = kp >> 3, uu = PERM(kp & 7);
        #pragma unroll
        for (int j = 0; j < 4; ++j) {
            float x0 = (j == 0) ? v0.x : (j == 1) ? v0.y : (j == 2) ? v0.z : v0.w;
            float x1 = (j == 0) ? v1.x : (j == 1) ? v1.y : (j == 2) ? v1.z : v1.w;
            int d = 4 * dq + j;
            int e = uu ^ (((d >> 2) & 3) << 1);
            uint32_t o = (uint32_t)(bh * DH + d) * VROW + ch * 16 + ((e >> 1) << 2) + (e & 1);
            uint32_t h = pk(x0, x1);
            d_Vt[o] = h;
            d_Vt[o + 2] = pkres(x0, x1, h);
        }
    }
}

// GEMM2 k16 step (A = P frags; FA/FB outside [0,4] -> zeros)
#define G2STEP(FA, FB, C2) do {                                                   \
    int ck = chunk0 + (C2);                                                       \
    if (ck * 16 + 15 >= glo && ck * 16 <= ghi) {                                  \
        uint32_t ah0, ah1, ah2, ah3, al0, al1, al2, al3;                          \
        if ((FA) >= 0) {                                                          \
            float4 pa = C[FI(FA)];                                                \
            ah0 = pk(pa.x, pa.y); al0 = pkres(pa.x, pa.y, ah0);                   \
            ah1 = pk(pa.z, pa.w); al1 = pkres(pa.z, pa.w, ah1);                   \
        } else { ah0 = ah1 = al0 = al1 = 0u; }                                    \
        if ((FB) <= 4) {                                                          \
            float4 pb = C[FI(FB)];                                                \
            ah2 = pk(pb.x, pb.y); al2 = pkres(pb.x, pb.y, ah2);                   \
            ah3 = pk(pb.z, pb.w); al3 = pkres(pb.z, pb.w, ah3);                   \
        } else { ah2 = ah3 = al2 = al3 = 0u; }                                    \
        _Pragma("unroll")                                                         \
        for (int nt = 0; nt < 8; ++nt) {                                          \
            uint32_t dr = nt * 8 + gid;                                           \
            uint32_t bi = dr * SV + ck * 16 + ((tig ^ ((dr >> 2) & 3u)) << 2);    \
            uint4 bv = *(const uint4*)(su + bi);                                  \
            mmabf(acc[nt], ah0, ah1, ah2, ah3, bv.x, bv.y);                       \
            mmabf(acc[nt], al0, al1, al2, al3, bv.x, bv.y);                       \
            mmabf(acc[nt], ah0, ah1, ah2, ah3, bv.z, bv.w);                       \
        }                                                                         \
    }                                                                             \
} while (0)

__global__ void __launch_bounds__(NT, 2)
band_attn_bf16(const float* __restrict__ Q, const float* __restrict__ K,
               const float* __restrict__ V, float* __restrict__ ctx_out,
               float* __restrict__ attn_out)
{
    extern __shared__ float smem[];
    uint32_t* su = (uint32_t*)smem;
    float*    sf = smem;

    const int tid = threadIdx.x, w = tid >> 5, lane = tid & 31;
    const int gid = lane >> 2, tig = lane & 3;
    const int m = w >> 3, nw = w & 7;
    const int bh = blockIdx.z * NH + blockIdx.y;
    const int q0 = blockIdx.x * TQ;
    const int klo = max(0, q0 - 128);
    const int klo2 = klo >> 1;                 // multiple of 8
    const int khi = min(S_LEN - 1, q0 + TQ - 1 + WIN - 1);
    const int cnt = khi - klo + 1;             // <= 287

    float* attn = attn_out + (size_t)bh * S_LEN * S_LEN;

    // ---- K tile copy (interleaved rows, uint4) ----
    for (int i = tid; i < cnt * 16; i += NT) {
        int r = i >> 4, c = i & 15;
        ((uint4*)(su + O_K + r * SK))[c] =
            ((const uint4*)(d_Kp + ((size_t)(bh * S_LEN) + klo + r) * 64))[c];
    }
    // ---- Q convert in-kernel (1 item/thread), interleaved layout ----
    {
        int r = tid >> 4, dq = tid & 15;
        float4 v = ((const float4*)Q)[((size_t)(bh * S_LEN) + q0 + r) * 16 + dq];
        float x0 = v.x * 0.125f, x1 = v.y * 0.125f, x2 = v.z * 0.125f, x3 = v.w * 0.125f;
        int ks = dq >> 2;
        int p0 = PERM((2 * dq) & 7), p1 = PERM((2 * dq + 1) & 7);
        uint32_t* qr2 = su + O_Q + r * SK;
        uint32_t g0 = pk(x0, x1), g1 = pk(x2, x3);
        int o0 = ks * 16 + ((p0 >> 1) << 2) + (p0 & 1);
        int o1 = ks * 16 + ((p1 >> 1) << 2) + (p1 & 1);
        qr2[o0] = g0; qr2[o0 + 2] = pkres(x0, x1, g0);
        qr2[o1] = g1; qr2[o1 + 2] = pkres(x2, x3, g1);
    }
    // ---- zero-fill attn outside the 320-wide strip ----
    {
        float* t0 = attn + (size_t)q0 * S_LEN;
        if (4 * tid + 3 < klo || 4 * tid >= klo + KW) {
            const float4 z4 = make_float4(0.f, 0.f, 0.f, 0.f);
            #pragma unroll 8
            for (int r = 0; r < TQ; ++r)
                ((float4*)(t0 + (size_t)r * S_LEN))[tid] = z4;
        }
    }
    __syncthreads();

    // ---- warp geometry ----
    const int qr = m * 16, nb = nw * 40;
    const int glo = max(0, q0 + qr - 127) - klo;
    const int ghi = min(S_LEN - 1, q0 + qr + 15 + 127) - klo;
    bool alive[5];
    #pragma unroll
    for (int f = 0; f < 5; ++f)
        alive[f] = (nb + 8 * f + 7 >= glo) && (nb + 8 * f <= ghi);

    // ---- GEMM1: C[32x320] = Qs . K^T (bf16 3-term, LDS.128 frags) ----
    float4 C[5];
    #pragma unroll
    for (int f = 0; f < 5; ++f) C[f] = make_float4(0.f, 0.f, 0.f, 0.f);

    #pragma unroll
    for (int ks = 0; ks < 4; ++ks) {
        uint4 qv0 = *(const uint4*)(su + O_Q + (qr + gid) * SK + ks * 16 + tig * 4);
        uint4 qv1 = *(const uint4*)(su + O_Q + (qr + gid + 8) * SK + ks * 16 + tig * 4);
        #pragma unroll
        for (int f = 0; f < 5; ++f) {
            if (!alive[f]) continue;
            uint4 kv = *(const uint4*)(su + O_K + (nb + 8 * f + gid) * SK + ks * 16 + tig * 4);
            mmabf(C[f], qv0.x, qv1.x, qv0.y, qv1.y, kv.x, kv.y);   // hh
            mmabf(C[f], qv0.z, qv1.z, qv0.w, qv1.w, kv.x, kv.y);   // lh
            mmabf(C[f], qv0.x, qv1.x, qv0.y, qv1.y, kv.z, kv.w);   // hl
        }
    }

    // ---- band mask + local row stats ----
    const int r0g = q0 + qr + gid;
    float mr0 = -INFINITY, mr1 = -INFINITY;
    #pragma unroll
    for (int f = 0; f < 5; ++f) {
        int k0 = klo + nb + 8 * f + 2 * tig;
        bool v0 = (unsigned)(r0g     - k0     + WIN - 1) <= 2 * (WIN - 1) && k0     <= khi;
        bool v1 = (unsigned)(r0g     - k0 - 1 + WIN - 1) <= 2 * (WIN - 1) && k0 + 1 <= khi;
        bool v2 = (unsigned)(r0g + 8 - k0     + WIN - 1) <= 2 * (WIN - 1) && k0     <= khi;
        bool v3 = (unsigned)(r0g + 8 - k0 - 1 + WIN - 1) <= 2 * (WIN - 1) && k0 + 1 <= khi;
        C[f].x = v0 ? C[f].x : -INFINITY;
        C[f].y = v1 ? C[f].y : -INFINITY;
        C[f].z = v2 ? C[f].z : -INFINITY;
        C[f].w = v3 ? C[f].w : -INFINITY;
        mr0 = fmaxf(mr0, fmaxf(C[f].x, C[f].y));
        mr1 = fmaxf(mr1, fmaxf(C[f].z, C[f].w));
    }
    #pragma unroll
    for (int off = 1; off <= 2; off <<= 1) {
        mr0 = fmaxf(mr0, __shfl_xor_sync(0xffffffffu, mr0, off));
        mr1 = fmaxf(mr1, __shfl_xor_sync(0xffffffffu, mr1, off));
    }
    mr0 = fmaxf(mr0, -1e30f); mr1 = fmaxf(mr1, -1e30f);
    float sr0 = 0.f, sr1 = 0.f;
    #pragma unroll
    for (int f = 0; f < 5; ++f) {
        sr0 += __expf(C[f].x - mr0) + __expf(C[f].y - mr0);
        sr1 += __expf(C[f].z - mr1) + __expf(C[f].w - mr1);
    }
    #pragma unroll
    for (int off = 1; off <= 2; off <<= 1) {
        sr0 += __shfl_xor_sync(0xffffffffu, sr0, off);
        sr1 += __shfl_xor_sync(0xffffffffu, sr1, off);
    }
    if (tig == 0) {
        sf[O_MS + nw * 32 + qr + gid]     = mr0;  sf[O_SS + nw * 32 + qr + gid]     = sr0;
        sf[O_MS + nw * 32 + qr + gid + 8] = mr1;  sf[O_SS + nw * 32 + qr + gid + 8] = sr1;
    }
    __syncthreads();   // K dead; stats visible

    // ---- Vt copy into K region (uint4, 10 per thread, coalesced) ----
    {
        int d = tid >> 3, c0 = tid & 7;
        const uint4* src = (const uint4*)(d_Vt + (size_t)(bh * DH + d) * VROW + klo2 * 2);
        uint4* dst = (uint4*)(su + d * SV);
        #pragma unroll
        for (int j = 0; j < 10; ++j) dst[c0 + j * 8] = src[c0 + j * 8];
    }

    // ---- global softmax constant per row ----
    float M0 = -INFINITY, M1 = -INFINITY;
    #pragma unroll
    for (int n2 = 0; n2 < 8; ++n2) {
        M0 = fmaxf(M0, sf[O_MS + n2 * 32 + qr + gid]);
        M1 = fmaxf(M1, sf[O_MS + n2 * 32 + qr + gid + 8]);
    }
    float S0 = 0.f, S1 = 0.f;
    #pragma unroll
    for (int n2 = 0; n2 < 8; ++n2) {
        S0 += sf[O_SS + n2 * 32 + qr + gid]     * __expf(sf[O_MS + n2 * 32 + qr + gid]     - M0);
        S1 += sf[O_SS + n2 * 32 + qr + gid + 8] * __expf(sf[O_MS + n2 * 32 + qr + gid + 8] - M1);
    }
    const float Cr0 = M0 + __logf(S0);
    const float Cr1 = M1 + __logf(S1);
    __syncthreads();   // Vt ready

    // ---- p = exp(C - Cr), attn band stores ----
    #pragma unroll
    for (int f = 0; f < 5; ++f) {
        float p0 = __expf(C[f].x - Cr0), p1 = __expf(C[f].y - Cr0);
        float p2 = __expf(C[f].z - Cr1), p3 = __expf(C[f].w - Cr1);
        C[f] = make_float4(p0, p1, p2, p3);
        int k0 = klo + nb + 8 * f + 2 * tig;
        if (k0 < S_LEN) {
            *(float2*)(attn + (size_t)r0g       * S_LEN + k0) = make_float2(p0, p1);
            *(float2*)(attn + (size_t)(r0g + 8) * S_LEN + k0) = make_float2(p2, p3);
        }
    }

    // ---- GEMM2: ctx = P . V (LDS.128 B frags) ----
    float4 acc[8];
    #pragma unroll
    for (int nt = 0; nt < 8; ++nt) acc[nt] = make_float4(0.f, 0.f, 0.f, 0.f);
    const int chunk0 = (nb - 8 * (nw & 1)) >> 4;
    if (!(nw & 1)) { G2STEP(0, 1, 0); G2STEP(2, 3, 1); G2STEP(4, 5, 2); }
    else           { G2STEP(-1, 0, 0); G2STEP(1, 2, 1); G2STEP(3, 4, 2); }
    __syncthreads();   // Vt dead

    // ---- combine 8 nw partials ----
    if (nw) {
        float4* sp = (float4*)sf + (m * 7 + nw - 1) * 256;
        #pragma unroll
        for (int nt = 0; nt < 8; ++nt) sp[nt * 32 + lane] = acc[nt];
    }
    __syncthreads();
    if (!nw) {
        #pragma unroll
        for (int s = 0; s < 7; ++s) {
            const float4* sp = (const float4*)sf + (m * 7 + s) * 256;
            #pragma unroll
            for (int nt = 0; nt < 8; ++nt) {
                float4 t = sp[nt * 32 + lane];
                acc[nt].x += t.x; acc[nt].y += t.y; acc[nt].z += t.z; acc[nt].w += t.w;
            }
        }
        float* cb = ctx_out + ((size_t)bh * S_LEN + q0 + qr) * DH;
        #pragma unroll
        for (int nt = 0; nt < 8; ++nt) {
            int d0 = nt * 8 + 2 * tig;
            *(float2*)(cb + gid * DH + d0)       = make_float2(acc[nt].x, acc[nt].y);
            *(float2*)(cb + (gid + 8) * DH + d0) = make_float2(acc[nt].z, acc[nt].w);
        }
    }
}

extern "C" void kernel_launch(void* const* d_in, const int* in_sizes, int n_in,
                              void* d_out, int out_size)
{
    const float* Q = (const float*)d_in[0];
    const float* K = (const float*)d_in[1];
    const float* V = (const float*)d_in[2];

    float* out  = (float*)d_out;
    float* ctx  = out;                                 // [B,H,S,D] first
    float* attn = out + (size_t)NB * NH * S_LEN * DH;  // then [B,H,S,S]

    prep_kernel<<<(NB * NH * S_LEN * 16) / 256, 256>>>(K, V);

    cudaFuncSetAttribute(band_attn_bf16,
                         cudaFuncAttributeMaxDynamicSharedMemorySize, SMEM_B);
    dim3 grid(S_LEN / TQ, NH, NB);
    band_attn_bf16<<<grid, NT, SMEM_B>>>(Q, K, V, ctx, attn);
}